// round 1
// baseline (speedup 1.0000x reference)
#include <cuda_runtime.h>

#define BATCH 4
#define CH    256
#define CD    32          // C/8
#define NPIX  4096        // H*W
#define FTOT  321         // 32 q + 32 k + 256 v + 1 pm
#define OUTOFF ((size_t)BATCH*CH*NPIX)

// ---------------- device scratch (no allocation allowed) ----------------
__device__ float g_W[FTOT*CH];                       // packed weights [f][c]
__device__ float g_bias[FTOT];
__device__ float g_Y[(size_t)BATCH*FTOT*NPIX];       // [b][f][n]  ~21 MB
__device__ float g_vmask[BATCH*CH];                  // sum_n v[b,c,n]*mask[b,n]

// ---------------- pack weights/bias into one matrix ----------------
__global__ void pack_kernel(const float* __restrict__ wq, const float* __restrict__ bq,
                            const float* __restrict__ wk, const float* __restrict__ bk,
                            const float* __restrict__ wv, const float* __restrict__ bv,
                            const float* __restrict__ wm, const float* __restrict__ bm) {
    int i  = blockIdx.x*blockDim.x + threadIdx.x;
    int nt = gridDim.x*blockDim.x;
    for (int idx = i; idx < FTOT*CH; idx += nt) {
        int f = idx / CH, c = idx - f*CH;
        float v;
        if      (f < 32)  v = wq[f*CH + c];
        else if (f < 64)  v = wk[(f-32)*CH + c];
        else if (f < 320) v = wv[(f-64)*CH + c];
        else              v = wm[c];
        g_W[idx] = v;
    }
    if (i < FTOT) {
        g_bias[i] = (i < 32) ? bq[i] : (i < 64) ? bk[i-32] : (i < 320) ? bv[i-64] : bm[0];
    }
}

// ---------------- QKV/pm GEMM: Y[b,f,n] = sum_c W[f,c]*x[b,c,n] + bias ----------------
// block tile: 64 f x 64 n, c-chunks of 32; thread tile 4f x 4n
__global__ void __launch_bounds__(256) gemm_kernel(const float* __restrict__ x) {
    __shared__ float xs[32][64];
    __shared__ float ws[32][68];   // [c][f], padded
    int b  = blockIdx.z;
    int f0 = blockIdx.y * 64;
    int n0 = blockIdx.x * 64;
    int t  = threadIdx.x;
    int tf = t >> 4, tn = t & 15;
    float acc[4][4] = {};
    const float* xb = x + (size_t)b*CH*NPIX;

    for (int c0 = 0; c0 < CH; c0 += 32) {
        #pragma unroll
        for (int k2 = 0; k2 < 2; k2++) {               // xs: 512 float4
            int i = t + k2*256;
            int r = i >> 4, q = i & 15;
            *(float4*)&xs[r][q*4] = *(const float4*)&xb[(size_t)(c0+r)*NPIX + n0 + q*4];
        }
        #pragma unroll
        for (int k2 = 0; k2 < 2; k2++) {               // ws: transpose W rows into [c][f]
            int i = t + k2*256;
            int f = i >> 3, j = i & 7;
            float4 v = make_float4(0.f,0.f,0.f,0.f);
            if (f0 + f < FTOT) v = *(const float4*)&g_W[(f0+f)*CH + c0 + j*4];
            ws[j*4+0][f]=v.x; ws[j*4+1][f]=v.y; ws[j*4+2][f]=v.z; ws[j*4+3][f]=v.w;
        }
        __syncthreads();
        #pragma unroll
        for (int cc = 0; cc < 32; cc++) {
            float4 w4 = *(float4*)&ws[cc][tf*4];
            float4 x4 = *(float4*)&xs[cc][tn*4];
            float wr[4] = {w4.x,w4.y,w4.z,w4.w};
            float xr[4] = {x4.x,x4.y,x4.z,x4.w};
            #pragma unroll
            for (int fi = 0; fi < 4; fi++)
                #pragma unroll
                for (int ni = 0; ni < 4; ni++)
                    acc[fi][ni] += wr[fi]*xr[ni];
        }
        __syncthreads();
    }
    #pragma unroll
    for (int fi = 0; fi < 4; fi++) {
        int f = f0 + tf*4 + fi;
        if (f < FTOT) {
            float bia = g_bias[f];
            bool rel = (f >= 64 && f < 320);           // relu only on V rows
            #pragma unroll
            for (int ni = 0; ni < 4; ni++) {
                float v = acc[fi][ni] + bia;
                if (rel) v = fmaxf(v, 0.f);
                g_Y[((size_t)b*FTOT + f)*NPIX + n0 + tn*4 + ni] = v;
            }
        }
    }
}

// ---------------- center q (f 0..31) and k (f 32..63) over n ----------------
__global__ void __launch_bounds__(256) center_kernel() {
    int f = blockIdx.x;          // 0..63
    int b = blockIdx.y;
    float* row = g_Y + ((size_t)b*FTOT + f)*NPIX;
    __shared__ float red[256];
    int t = threadIdx.x;
    float s = 0.f;
    for (int i = t; i < NPIX/4; i += 256) {
        float4 v = ((const float4*)row)[i];
        s += (v.x+v.y)+(v.z+v.w);
    }
    red[t] = s; __syncthreads();
    for (int o = 128; o > 0; o >>= 1) { if (t < o) red[t] += red[t+o]; __syncthreads(); }
    float mean = red[0] * (1.f/NPIX);
    for (int i = t; i < NPIX/4; i += 256) {
        float4 v = ((const float4*)row)[i];
        v.x -= mean; v.y -= mean; v.z -= mean; v.w -= mean;
        ((float4*)row)[i] = v;
    }
}

// ---------------- softmax over pm row (f=320) -> mask ----------------
__global__ void __launch_bounds__(256) masksoftmax_kernel() {
    int b = blockIdx.x;
    float* row = g_Y + ((size_t)b*FTOT + 320)*NPIX;
    __shared__ float red[256];
    int t = threadIdx.x;
    float mx = -1e30f;
    for (int i = t; i < NPIX; i += 256) mx = fmaxf(mx, row[i]);
    red[t] = mx; __syncthreads();
    for (int o = 128; o > 0; o >>= 1) { if (t < o) red[t] = fmaxf(red[t], red[t+o]); __syncthreads(); }
    mx = red[0]; __syncthreads();
    float s = 0.f;
    for (int i = t; i < NPIX; i += 256) { float e = __expf(row[i]-mx); row[i] = e; s += e; }
    red[t] = s; __syncthreads();
    for (int o = 128; o > 0; o >>= 1) { if (t < o) red[t] += red[t+o]; __syncthreads(); }
    float inv = 1.f/red[0];
    for (int i = t; i < NPIX; i += 256) row[i] *= inv;
}

// ---------------- vmask[b,c] = sum_n v[b,c,n]*mask[b,n] ----------------
__global__ void __launch_bounds__(256) vmask_kernel() {
    int c = blockIdx.x, b = blockIdx.y;
    const float* vrow = g_Y + ((size_t)b*FTOT + 64 + c)*NPIX;
    const float* mrow = g_Y + ((size_t)b*FTOT + 320)*NPIX;
    __shared__ float red[256];
    int t = threadIdx.x;
    float s = 0.f;
    for (int i = t; i < NPIX/4; i += 256) {
        float4 v = ((const float4*)vrow)[i];
        float4 m = ((const float4*)mrow)[i];
        s += v.x*m.x + v.y*m.y + v.z*m.z + v.w*m.w;
    }
    red[t] = s; __syncthreads();
    for (int o = 128; o > 0; o >>= 1) { if (t < o) red[t] += red[t+o]; __syncthreads(); }
    if (t == 0) g_vmask[b*CH + c] = red[0];
}

// ---------------- attention: O[c,m] = (sum_n exp(q_m.k_n) v[c,n]) / den_m + vmask ----------------
// block: one batch x 64-query tile. Key tiles of 64. Logits bounded (~|4|) -> no max subtraction.
// smem floats: qs 32*68, ks 32*68, ps 64*72 ([n][m]), vs 256*65 ([c][n]), den 64
#define ATTN_SMEM ((32*68 + 32*68 + 64*72 + 256*65 + 64) * 4)

__global__ void __launch_bounds__(256,2) attn_kernel(float* __restrict__ out) {
    extern __shared__ float smf[];
    float* qs    = smf;                 // [d][m] pad 68
    float* ks    = qs + 32*68;          // [d][n] pad 68
    float* ps    = ks + 32*68;          // [n][m] pad 72
    float* vs    = ps + 64*72;          // [c][n] pad 65
    float* den_s = vs + 256*65;         // [64]

    int b  = blockIdx.y;
    int m0 = blockIdx.x * 64;
    int t  = threadIdx.x;
    const float* Yb = g_Y + (size_t)b*FTOT*NPIX;

    #pragma unroll
    for (int k2 = 0; k2 < 2; k2++) {    // load Q tile [32 d][64 m]
        int i = t + k2*256;
        int d = i >> 4, q = i & 15;
        *(float4*)&qs[d*68 + q*4] = *(const float4*)&Yb[(size_t)d*NPIX + m0 + q*4];
    }

    float acc[8][8];
    #pragma unroll
    for (int i = 0; i < 8; i++)
        #pragma unroll
        for (int j = 0; j < 8; j++) acc[i][j] = 0.f;
    float den = 0.f;

    int tm   = t >> 5;          // m-group: rows tm*8..tm*8+7 (same for whole warp -> p broadcast)
    int lane = t & 31;          // c = lane + 32*j  (lane-strided -> conflict-free v reads)
    int mg4  = (t >> 4) * 4;    // S phase: 4m x 4n per thread
    int ng4  = (t & 15) * 4;

    for (int n0 = 0; n0 < NPIX; n0 += 64) {
        #pragma unroll
        for (int k2 = 0; k2 < 2; k2++) {        // K tile [32 d][64 n]
            int i = t + k2*256;
            int d = i >> 4, q = i & 15;
            *(float4*)&ks[d*68 + q*4] = *(const float4*)&Yb[(size_t)(32+d)*NPIX + n0 + q*4];
        }
        #pragma unroll
        for (int k2 = 0; k2 < 16; k2++) {       // V tile [256 c][64 n]
            int i = t + k2*256;
            int c = i >> 4, q = i & 15;
            float4 v = *(const float4*)&Yb[(size_t)(64+c)*NPIX + n0 + q*4];
            float* dst = &vs[c*65 + q*4];
            dst[0]=v.x; dst[1]=v.y; dst[2]=v.z; dst[3]=v.w;
        }
        __syncthreads();

        // S = Q^T K (4x4 per thread), p = exp(s), store transposed ps[n][m]
        float sreg[4][4] = {};
        #pragma unroll
        for (int d = 0; d < 32; d++) {
            float4 q4 = *(float4*)&qs[d*68 + mg4];
            float4 k4 = *(float4*)&ks[d*68 + ng4];
            float qr[4] = {q4.x,q4.y,q4.z,q4.w};
            float kr[4] = {k4.x,k4.y,k4.z,k4.w};
            #pragma unroll
            for (int i2 = 0; i2 < 4; i2++)
                #pragma unroll
                for (int j2 = 0; j2 < 4; j2++)
                    sreg[i2][j2] += qr[i2]*kr[j2];
        }
        #pragma unroll
        for (int i2 = 0; i2 < 4; i2++)
            #pragma unroll
            for (int j2 = 0; j2 < 4; j2++)
                ps[(ng4+j2)*72 + mg4+i2] = __expf(sreg[i2][j2]);
        __syncthreads();

        if (t < 64) {                           // denominator rows
            float s = 0.f;
            #pragma unroll
            for (int n = 0; n < 64; n += 4)
                s += ps[n*72+t] + ps[(n+1)*72+t] + ps[(n+2)*72+t] + ps[(n+3)*72+t];
            den += s;
        }

        #pragma unroll 2
        for (int n = 0; n < 64; n++) {          // acc += p[m] * v[c,n]
            float4 p0 = *(float4*)&ps[n*72 + tm*8];
            float4 p1 = *(float4*)&ps[n*72 + tm*8 + 4];
            float pv[8] = {p0.x,p0.y,p0.z,p0.w,p1.x,p1.y,p1.z,p1.w};
            #pragma unroll
            for (int j = 0; j < 8; j++) {
                float vv = vs[(lane + 32*j)*65 + n];
                #pragma unroll
                for (int mi = 0; mi < 8; mi++)
                    acc[mi][j] += pv[mi]*vv;
            }
        }
        __syncthreads();
    }

    if (t < 64) den_s[t] = den;
    __syncthreads();

    float* tis = out + OUTOFF + (size_t)b*CH*NPIX;
    #pragma unroll
    for (int mi = 0; mi < 8; mi++) {
        int m = tm*8 + mi;
        float inv = 1.0f / den_s[m];
        #pragma unroll
        for (int j = 0; j < 8; j++) {
            int c = lane + 32*j;
            tis[(size_t)c*NPIX + m0 + m] = acc[mi][j]*inv + g_vmask[b*CH + c];
        }
    }
}

// ---------------- launch ----------------
extern "C" void kernel_launch(void* const* d_in, const int* in_sizes, int n_in,
                              void* d_out, int out_size) {
    const float* x  = (const float*)d_in[0];
    const float* wq = (const float*)d_in[1];
    const float* bq = (const float*)d_in[2];
    const float* wk = (const float*)d_in[3];
    const float* bk = (const float*)d_in[4];
    const float* wv = (const float*)d_in[5];
    const float* bv = (const float*)d_in[6];
    const float* wm = (const float*)d_in[7];
    const float* bm = (const float*)d_in[8];
    float* out = (float*)d_out;

    cudaFuncSetAttribute(attn_kernel, cudaFuncAttributeMaxDynamicSharedMemorySize, ATTN_SMEM);

    // out = (x, tissue): copy x into first half
    cudaMemcpyAsync(out, x, OUTOFF*sizeof(float), cudaMemcpyDeviceToDevice, 0);

    pack_kernel<<<128, 256>>>(wq, bq, wk, bk, wv, bv, wm, bm);
    gemm_kernel<<<dim3(NPIX/64, 6, BATCH), 256>>>(x);
    center_kernel<<<dim3(64, BATCH), 256>>>();
    masksoftmax_kernel<<<BATCH, 256>>>();
    vmask_kernel<<<dim3(CH, BATCH), 256>>>();
    attn_kernel<<<dim3(NPIX/64, BATCH), 256, ATTN_SMEM>>>(out);
}

// round 5
// speedup vs baseline: 4.9097x; 4.9097x over previous
#include <cuda_runtime.h>
#include <cstdint>

#define BATCH 4
#define CH    256
#define NPIX  4096
#define FTOT  321
#define OUTOFF ((size_t)BATCH*CH*NPIX)
#define LOG2E 1.4426950408889634f

// ---------------- device scratch ----------------
__device__ float g_W[FTOT*CH];
__device__ float g_bias[FTOT];
__device__ float g_Y[(size_t)BATCH*FTOT*NPIX];
__device__ float g_vmask[BATCH*CH];
__device__ __align__(16) uint32_t g_Qb[(size_t)BATCH*NPIX*16];   // [b][n][16] bf16x2 pairs of d (q pre-scaled by log2e)
__device__ __align__(16) uint32_t g_Kb[(size_t)BATCH*NPIX*16];
__device__ __align__(16) uint16_t g_Vb[(size_t)BATCH*CH*NPIX];   // bf16 [b][c][n]

// ---------------- helpers ----------------
__device__ __forceinline__ uint32_t smem_u32(const void* p) {
    uint32_t a;
    asm("{ .reg .u64 t; cvta.to.shared.u64 t, %1; cvt.u32.u64 %0, t; }" : "=r"(a) : "l"(p));
    return a;
}
__device__ __forceinline__ void ldsm4(uint32_t* r, uint32_t addr) {
    asm volatile("ldmatrix.sync.aligned.m8n8.x4.shared.b16 {%0,%1,%2,%3}, [%4];"
        : "=r"(r[0]), "=r"(r[1]), "=r"(r[2]), "=r"(r[3]) : "r"(addr));
}
__device__ __forceinline__ void mma16816(float* c, const uint32_t* a, uint32_t b0, uint32_t b1) {
    asm volatile("mma.sync.aligned.m16n8k16.row.col.f32.bf16.bf16.f32 "
        "{%0,%1,%2,%3}, {%4,%5,%6,%7}, {%8,%9}, {%0,%1,%2,%3};"
        : "+f"(c[0]), "+f"(c[1]), "+f"(c[2]), "+f"(c[3])
        : "r"(a[0]), "r"(a[1]), "r"(a[2]), "r"(a[3]), "r"(b0), "r"(b1));
}
__device__ __forceinline__ float ex2f(float x) {
    float r; asm("ex2.approx.f32 %0, %1;" : "=f"(r) : "f"(x)); return r;
}
#define CPA16(dst, src) asm volatile("cp.async.cg.shared.global [%0], [%1], 16;" :: "r"(dst), "l"(src))
#define CPA_COMMIT()    asm volatile("cp.async.commit_group;")
#define CPA_WAIT1()     asm volatile("cp.async.wait_group 1;")

// ---------------- pack (q weights/bias pre-scaled by log2e) ----------------
__global__ void pack_kernel(const float* __restrict__ wq, const float* __restrict__ bq,
                            const float* __restrict__ wk, const float* __restrict__ bk,
                            const float* __restrict__ wv, const float* __restrict__ bv,
                            const float* __restrict__ wm, const float* __restrict__ bm) {
    int i  = blockIdx.x*blockDim.x + threadIdx.x;
    int nt = gridDim.x*blockDim.x;
    for (int idx = i; idx < FTOT*CH; idx += nt) {
        int f = idx / CH, c = idx - f*CH;
        float v;
        if      (f < 32)  v = wq[f*CH + c] * LOG2E;
        else if (f < 64)  v = wk[(f-32)*CH + c];
        else if (f < 320) v = wv[(f-64)*CH + c];
        else              v = wm[c];
        g_W[idx] = v;
    }
    if (i < FTOT)
        g_bias[i] = (i < 32) ? bq[i]*LOG2E : (i < 64) ? bk[i-32] : (i < 320) ? bv[i-64] : bm[0];
}

// ---------------- QKV/pm GEMM (fp32 SIMT) ----------------
__global__ void __launch_bounds__(256) gemm_kernel(const float* __restrict__ x) {
    __shared__ float xs[32][64];
    __shared__ float ws[32][68];
    int b  = blockIdx.z;
    int f0 = blockIdx.y * 64;
    int n0 = blockIdx.x * 64;
    int t  = threadIdx.x;
    int tf = t >> 4, tn = t & 15;
    float acc[4][4] = {};
    const float* xb = x + (size_t)b*CH*NPIX;

    for (int c0 = 0; c0 < CH; c0 += 32) {
        #pragma unroll
        for (int k2 = 0; k2 < 2; k2++) {
            int i = t + k2*256;
            int r = i >> 4, q = i & 15;
            *(float4*)&xs[r][q*4] = *(const float4*)&xb[(size_t)(c0+r)*NPIX + n0 + q*4];
        }
        #pragma unroll
        for (int k2 = 0; k2 < 2; k2++) {
            int i = t + k2*256;
            int f = i >> 3, j = i & 7;
            float4 v = make_float4(0.f,0.f,0.f,0.f);
            if (f0 + f < FTOT) v = *(const float4*)&g_W[(f0+f)*CH + c0 + j*4];
            ws[j*4+0][f]=v.x; ws[j*4+1][f]=v.y; ws[j*4+2][f]=v.z; ws[j*4+3][f]=v.w;
        }
        __syncthreads();
        #pragma unroll
        for (int cc = 0; cc < 32; cc++) {
            float4 w4 = *(float4*)&ws[cc][tf*4];
            float4 x4 = *(float4*)&xs[cc][tn*4];
            float wr[4] = {w4.x,w4.y,w4.z,w4.w};
            float xr[4] = {x4.x,x4.y,x4.z,x4.w};
            #pragma unroll
            for (int fi = 0; fi < 4; fi++)
                #pragma unroll
                for (int ni = 0; ni < 4; ni++)
                    acc[fi][ni] += wr[fi]*xr[ni];
        }
        __syncthreads();
    }
    #pragma unroll
    for (int fi = 0; fi < 4; fi++) {
        int f = f0 + tf*4 + fi;
        if (f < FTOT) {
            float bia = g_bias[f];
            bool rel = (f >= 64 && f < 320);
            #pragma unroll
            for (int ni = 0; ni < 4; ni++) {
                float v = acc[fi][ni] + bia;
                if (rel) v = fmaxf(v, 0.f);
                g_Y[((size_t)b*FTOT + f)*NPIX + n0 + tn*4 + ni] = v;
            }
        }
    }
}

// ---------------- center q/k rows ----------------
__global__ void __launch_bounds__(256) center_kernel() {
    int f = blockIdx.x, b = blockIdx.y;
    float* row = g_Y + ((size_t)b*FTOT + f)*NPIX;
    __shared__ float red[256];
    int t = threadIdx.x;
    float s = 0.f;
    for (int i = t; i < NPIX/4; i += 256) {
        float4 v = ((const float4*)row)[i];
        s += (v.x+v.y)+(v.z+v.w);
    }
    red[t] = s; __syncthreads();
    for (int o = 128; o > 0; o >>= 1) { if (t < o) red[t] += red[t+o]; __syncthreads(); }
    float mean = red[0] * (1.f/NPIX);
    for (int i = t; i < NPIX/4; i += 256) {
        float4 v = ((const float4*)row)[i];
        v.x -= mean; v.y -= mean; v.z -= mean; v.w -= mean;
        ((float4*)row)[i] = v;
    }
}

// ---------------- mask softmax ----------------
__global__ void __launch_bounds__(256) masksoftmax_kernel() {
    int b = blockIdx.x;
    float* row = g_Y + ((size_t)b*FTOT + 320)*NPIX;
    __shared__ float red[256];
    int t = threadIdx.x;
    float mx = -1e30f;
    for (int i = t; i < NPIX; i += 256) mx = fmaxf(mx, row[i]);
    red[t] = mx; __syncthreads();
    for (int o = 128; o > 0; o >>= 1) { if (t < o) red[t] = fmaxf(red[t], red[t+o]); __syncthreads(); }
    mx = red[0]; __syncthreads();
    float s = 0.f;
    for (int i = t; i < NPIX; i += 256) { float e = __expf(row[i]-mx); row[i] = e; s += e; }
    red[t] = s; __syncthreads();
    for (int o = 128; o > 0; o >>= 1) { if (t < o) red[t] += red[t+o]; __syncthreads(); }
    float inv = 1.f/red[0];
    for (int i = t; i < NPIX; i += 256) row[i] *= inv;
}

// ---------------- vmask ----------------
__global__ void __launch_bounds__(256) vmask_kernel() {
    int c = blockIdx.x, b = blockIdx.y;
    const float* vrow = g_Y + ((size_t)b*FTOT + 64 + c)*NPIX;
    const float* mrow = g_Y + ((size_t)b*FTOT + 320)*NPIX;
    __shared__ float red[256];
    int t = threadIdx.x;
    float s = 0.f;
    for (int i = t; i < NPIX/4; i += 256) {
        float4 v = ((const float4*)vrow)[i];
        float4 m = ((const float4*)mrow)[i];
        s += v.x*m.x + v.y*m.y + v.z*m.z + v.w*m.w;
    }
    red[t] = s; __syncthreads();
    for (int o = 128; o > 0; o >>= 1) { if (t < o) red[t] += red[t+o]; __syncthreads(); }
    if (t == 0) g_vmask[b*CH + c] = red[0];
}

// ---------------- q/k -> bf16 transposed [n][d] ----------------
__global__ void __launch_bounds__(256) qkconv_kernel() {
    __shared__ float sm[32][132];
    int n0 = blockIdx.x*128;
    int isk = blockIdx.y;
    int b = blockIdx.z;
    int t = threadIdx.x;
    const float* Yq = g_Y + ((size_t)b*FTOT + isk*32)*NPIX;
    #pragma unroll
    for (int r = 0; r < 4; r++) {
        int i = t + r*256;
        int d = i >> 5, c4 = i & 31;
        float4 v = *(const float4*)&Yq[(size_t)d*NPIX + n0 + c4*4];
        sm[d][c4*4+0]=v.x; sm[d][c4*4+1]=v.y; sm[d][c4*4+2]=v.z; sm[d][c4*4+3]=v.w;
    }
    __syncthreads();
    uint32_t* dst = (isk ? g_Kb : g_Qb) + ((size_t)b*NPIX + n0)*16;
    #pragma unroll
    for (int r = 0; r < 8; r++) {
        int i = t + r*256;
        int n = i >> 4, jp = i & 15;
        uint32_t pk;
        asm("cvt.rn.bf16x2.f32 %0, %1, %2;" : "=r"(pk) : "f"(sm[2*jp+1][n]), "f"(sm[2*jp][n]));
        dst[n*16 + jp] = pk;
    }
}

// ---------------- v -> bf16 ----------------
__global__ void __launch_bounds__(256) vconv_kernel() {
    size_t i = (size_t)blockIdx.x*256 + threadIdx.x;
    int b = (int)(i >> 17);
    int r = (int)(i & 0x1FFFF);
    int c = r >> 9;
    int o8 = r & 511;
    const float* src = &g_Y[((size_t)b*FTOT + 64 + c)*NPIX + o8*8];
    float4 v0 = *(const float4*)src;
    float4 v1 = *(const float4*)(src+4);
    uint32_t p0,p1,p2,p3;
    asm("cvt.rn.bf16x2.f32 %0, %1, %2;" : "=r"(p0) : "f"(v0.y), "f"(v0.x));
    asm("cvt.rn.bf16x2.f32 %0, %1, %2;" : "=r"(p1) : "f"(v0.w), "f"(v0.z));
    asm("cvt.rn.bf16x2.f32 %0, %1, %2;" : "=r"(p2) : "f"(v1.y), "f"(v1.x));
    asm("cvt.rn.bf16x2.f32 %0, %1, %2;" : "=r"(p3) : "f"(v1.w), "f"(v1.z));
    uint4 o; o.x=p0; o.y=p1; o.z=p2; o.w=p3;
    *(uint4*)(g_Vb + ((size_t)b*CH + c)*NPIX + o8*8) = o;
}

// ---------------- attention via mma.sync (HMMA) ----------------
// smem: vmk[256]f, Qs [128m][64B swizzled], Ks x2 [128n][64B sw], Vs x2 [256c][256B sw]
#define SM_VMK 0
#define SM_QS  1024
#define SM_KS0 9216
#define SM_KS1 17408
#define SM_VS0 25600
#define SM_VS1 91136
#define SM_TOTAL 156672

__global__ void __launch_bounds__(256, 1) attn_kernel(float* __restrict__ out) {
    extern __shared__ __align__(128) char smem[];
    uint32_t sb = smem_u32(smem);
    float* vmk = (float*)(smem + SM_VMK);
    int t = threadIdx.x, w = t >> 5, lane = t & 31;
    int b = blockIdx.y, m0 = blockIdx.x * 128;

    vmk[t] = g_vmask[b*CH + t];

    // B-operand ldmatrix mapping (matrix order: rows-lo/col-lo, rows-lo/col-hi, rows-hi/col-lo, rows-hi/col-hi)
    int lq = lane >> 3, lr = lane & 7;
    uint32_t lrow   = (uint32_t)((lq >> 1)*8 + lr);
    uint32_t lcsel  = (uint32_t)((lq & 1)*16);
    // A-operand ldmatrix mapping (register order a0,a1,a2,a3: rows-lo/k-lo, rows-HI/k-lo, rows-lo/k-HI, rows-hi/k-hi)
    uint32_t arow   = (uint32_t)(lane & 15);
    uint32_t acsel  = (uint32_t)((lane >> 4)*16);
    uint32_t kxor   = (uint32_t)(((lr >> 1) & 3) << 4);   // 64B-row swizzle (lane bits 1,2)
    uint32_t vxor   = (uint32_t)(lr << 4);                // 256B-row swizzle

    // ---- prologue: Q + tile 0 (cp.async) ----
    #pragma unroll
    for (int kk = 0; kk < 2; kk++) {
        int idx = t + kk*256;
        int m = idx >> 2, j = idx & 3;
        const char* src = (const char*)(g_Qb + ((size_t)b*NPIX + m0 + m)*16 + j*4);
        uint32_t dst = sb + SM_QS + m*64 + ((j*16) ^ ((((uint32_t)m >> 1) & 3) << 4));
        CPA16(dst, src);
    }
    {
        uint32_t ksd = sb + SM_KS0, vsd = sb + SM_VS0;
        #pragma unroll
        for (int kk = 0; kk < 2; kk++) {
            int idx = t + kk*256;
            int n = idx >> 2, j = idx & 3;
            const char* src = (const char*)(g_Kb + ((size_t)b*NPIX + 0 + n)*16 + j*4);
            CPA16(ksd + n*64 + ((j*16) ^ ((((uint32_t)n >> 1) & 3) << 4)), src);
        }
        #pragma unroll
        for (int kk = 0; kk < 16; kk++) {
            int idx = t + kk*256;
            int c = idx >> 4, j = idx & 15;
            const char* src = (const char*)(g_Vb + ((size_t)b*CH + c)*NPIX + 0 + j*8);
            CPA16(vsd + c*256 + ((j*16) ^ (((uint32_t)c & 7) << 4)), src);
        }
    }
    CPA_COMMIT();

    float d2[32][4];
    #pragma unroll
    for (int i = 0; i < 32; i++)
        #pragma unroll
        for (int j = 0; j < 4; j++) d2[i][j] = 0.f;
    uint32_t aq[2][4];
    float den0 = 0.f, den1 = 0.f;

    #pragma unroll 1
    for (int i = 0; i < 32; i++) {
        // prefetch tile i+1 into other buffer
        if (i < 31) {
            int n0 = (i + 1) << 7;
            uint32_t ksd = sb + (((i + 1) & 1) ? SM_KS1 : SM_KS0);
            uint32_t vsd = sb + (((i + 1) & 1) ? SM_VS1 : SM_VS0);
            #pragma unroll
            for (int kk = 0; kk < 2; kk++) {
                int idx = t + kk*256;
                int n = idx >> 2, j = idx & 3;
                const char* src = (const char*)(g_Kb + ((size_t)b*NPIX + n0 + n)*16 + j*4);
                CPA16(ksd + n*64 + ((j*16) ^ ((((uint32_t)n >> 1) & 3) << 4)), src);
            }
            #pragma unroll
            for (int kk = 0; kk < 16; kk++) {
                int idx = t + kk*256;
                int c = idx >> 4, j = idx & 15;
                const char* src = (const char*)(g_Vb + ((size_t)b*CH + c)*NPIX + n0 + j*8);
                CPA16(vsd + c*256 + ((j*16) ^ (((uint32_t)c & 7) << 4)), src);
            }
        }
        CPA_COMMIT();
        CPA_WAIT1();
        __syncthreads();

        if (i == 0) {   // Q A-fragments (persist whole kernel) — A-style mapping
            uint32_t qbase = sb + SM_QS + (w*16 + arow)*64;
            ldsm4(aq[0], qbase + ((0  + acsel) ^ kxor));
            ldsm4(aq[1], qbase + ((32 + acsel) ^ kxor));
        }

        uint32_t ksb = sb + ((i & 1) ? SM_KS1 : SM_KS0);
        uint32_t vsb = sb + ((i & 1) ? SM_VS1 : SM_VS0);

        // ---- per 16-key block: MMA1 -> exp2 -> pack -> MMA2 over all 256 c ----
        #pragma unroll
        for (int h = 0; h < 8; h++) {
            float s0[4] = {0.f,0.f,0.f,0.f};
            float s1[4] = {0.f,0.f,0.f,0.f};
            uint32_t kb[4];
            uint32_t kbase = ksb + (h*16 + lrow)*64;
            ldsm4(kb, kbase + ((0 + lcsel) ^ kxor));
            mma16816(s0, aq[0], kb[0], kb[1]);
            mma16816(s1, aq[0], kb[2], kb[3]);
            ldsm4(kb, kbase + ((32 + lcsel) ^ kxor));
            mma16816(s0, aq[1], kb[0], kb[1]);
            mma16816(s1, aq[1], kb[2], kb[3]);
            float e00 = ex2f(s0[0]), e01 = ex2f(s0[1]), e02 = ex2f(s0[2]), e03 = ex2f(s0[3]);
            float e10 = ex2f(s1[0]), e11 = ex2f(s1[1]), e12 = ex2f(s1[2]), e13 = ex2f(s1[3]);
            den0 += (e00 + e01) + (e10 + e11);
            den1 += (e02 + e03) + (e12 + e13);
            uint32_t pk[4];
            asm("cvt.rn.bf16x2.f32 %0, %1, %2;" : "=r"(pk[0]) : "f"(e01), "f"(e00));
            asm("cvt.rn.bf16x2.f32 %0, %1, %2;" : "=r"(pk[1]) : "f"(e03), "f"(e02));
            asm("cvt.rn.bf16x2.f32 %0, %1, %2;" : "=r"(pk[2]) : "f"(e11), "f"(e10));
            asm("cvt.rn.bf16x2.f32 %0, %1, %2;" : "=r"(pk[3]) : "f"(e13), "f"(e12));

            uint32_t coloff = (uint32_t)(h*32 + lcsel);
            #pragma unroll
            for (int c16 = 0; c16 < 16; c16++) {
                uint32_t vb[4];
                ldsm4(vb, vsb + (c16*16 + lrow)*256 + (coloff ^ vxor));
                mma16816(d2[c16*2],     pk, vb[0], vb[1]);
                mma16816(d2[c16*2 + 1], pk, vb[2], vb[3]);
            }
        }
        __syncthreads();
    }

    // ---- epilogue: row sums -> divide, add vmask, store ----
    float rs0 = den0, rs1 = den1;
    rs0 += __shfl_xor_sync(0xffffffffu, rs0, 1);
    rs0 += __shfl_xor_sync(0xffffffffu, rs0, 2);
    rs1 += __shfl_xor_sync(0xffffffffu, rs1, 1);
    rs1 += __shfl_xor_sync(0xffffffffu, rs1, 2);
    float i0 = 1.f / rs0, i1 = 1.f / rs1;

    int mlo = m0 + w*16 + (lane >> 2);
    int cb  = 2*(lane & 3);
    float* outb = out + OUTOFF + (size_t)b*CH*NPIX;
    #pragma unroll
    for (int cc = 0; cc < 32; cc++) {
        int c0 = cc*8 + cb;
        outb[(size_t)c0*NPIX + mlo]           = d2[cc][0]*i0 + vmk[c0];
        outb[(size_t)(c0+1)*NPIX + mlo]       = d2[cc][1]*i0 + vmk[c0+1];
        outb[(size_t)c0*NPIX + mlo + 8]       = d2[cc][2]*i1 + vmk[c0];
        outb[(size_t)(c0+1)*NPIX + mlo + 8]   = d2[cc][3]*i1 + vmk[c0+1];
    }
}

// ---------------- launch ----------------
extern "C" void kernel_launch(void* const* d_in, const int* in_sizes, int n_in,
                              void* d_out, int out_size) {
    const float* x  = (const float*)d_in[0];
    const float* wq = (const float*)d_in[1];
    const float* bq = (const float*)d_in[2];
    const float* wk = (const float*)d_in[3];
    const float* bk = (const float*)d_in[4];
    const float* wv = (const float*)d_in[5];
    const float* bv = (const float*)d_in[6];
    const float* wm = (const float*)d_in[7];
    const float* bm = (const float*)d_in[8];
    float* out = (float*)d_out;

    cudaFuncSetAttribute(attn_kernel, cudaFuncAttributeMaxDynamicSharedMemorySize, SM_TOTAL);

    cudaMemcpyAsync(out, x, OUTOFF*sizeof(float), cudaMemcpyDeviceToDevice, 0);

    pack_kernel<<<128, 256>>>(wq, bq, wk, bk, wv, bv, wm, bm);
    gemm_kernel<<<dim3(NPIX/64, 6, BATCH), 256>>>(x);
    center_kernel<<<dim3(64, BATCH), 256>>>();
    masksoftmax_kernel<<<BATCH, 256>>>();
    vmask_kernel<<<dim3(CH, BATCH), 256>>>();
    qkconv_kernel<<<dim3(NPIX/128, 2, BATCH), 256>>>();
    vconv_kernel<<<2048, 256>>>();
    attn_kernel<<<dim3(NPIX/128, BATCH), 256, SM_TOTAL>>>(out);
}

// round 7
// speedup vs baseline: 6.6370x; 1.3518x over previous
#include <cuda_runtime.h>
#include <cstdint>

#define BATCH 4
#define CH    256
#define NPIX  4096
#define FTOT  321
#define FPAD  384
#define OUTOFF ((size_t)BATCH*CH*NPIX)
#define LOG2E 1.4426950408889634f

// ---------------- device scratch ----------------
__device__ __align__(16) uint16_t g_Wb[FPAD*CH];                 // bf16 packed weights [f][c] (q rows pre-scaled log2e)
__device__ float g_bias[FPAD];                                   // fp32 bias (v rows: bv, pm: bm, rest 0)
__device__ float g_xmean[BATCH*CH];                              // per-batch channel sums of x (atomic)
__device__ float g_cbias[BATCH*64];                              // -W[f].mean(x) for q/k rows
__device__ __align__(16) uint16_t g_Xt[(size_t)BATCH*NPIX*CH];   // bf16 x^T [b][n][c]
__device__ float g_Y[(size_t)BATCH*FTOT*NPIX];                   // fp32 (only rows 0..63 q/k + row 320 pm used)
__device__ float g_vmask[BATCH*CH];
__device__ __align__(16) uint32_t g_Qb[(size_t)BATCH*NPIX*16];   // [b][n][16] bf16x2 pairs of d
__device__ __align__(16) uint32_t g_Kb[(size_t)BATCH*NPIX*16];
__device__ __align__(16) uint16_t g_Vb[(size_t)BATCH*CH*NPIX];   // bf16 [b][c][n]

// ---------------- helpers ----------------
__device__ __forceinline__ uint32_t smem_u32(const void* p) {
    uint32_t a;
    asm("{ .reg .u64 t; cvta.to.shared.u64 t, %1; cvt.u32.u64 %0, t; }" : "=r"(a) : "l"(p));
    return a;
}
__device__ __forceinline__ void ldsm4(uint32_t* r, uint32_t addr) {
    asm volatile("ldmatrix.sync.aligned.m8n8.x4.shared.b16 {%0,%1,%2,%3}, [%4];"
        : "=r"(r[0]), "=r"(r[1]), "=r"(r[2]), "=r"(r[3]) : "r"(addr));
}
__device__ __forceinline__ void mma16816(float* c, const uint32_t* a, uint32_t b0, uint32_t b1) {
    asm volatile("mma.sync.aligned.m16n8k16.row.col.f32.bf16.bf16.f32 "
        "{%0,%1,%2,%3}, {%4,%5,%6,%7}, {%8,%9}, {%0,%1,%2,%3};"
        : "+f"(c[0]), "+f"(c[1]), "+f"(c[2]), "+f"(c[3])
        : "r"(a[0]), "r"(a[1]), "r"(a[2]), "r"(a[3]), "r"(b0), "r"(b1));
}
__device__ __forceinline__ float ex2f(float x) {
    float r; asm("ex2.approx.f32 %0, %1;" : "=f"(r) : "f"(x)); return r;
}
__device__ __forceinline__ float bflo(uint32_t u) { return __uint_as_float(u << 16); }
__device__ __forceinline__ float bfhi(uint32_t u) { return __uint_as_float(u & 0xFFFF0000u); }
__device__ __forceinline__ uint16_t f2bf(float v) {
    uint32_t pk;
    asm("cvt.rn.bf16x2.f32 %0, %1, %2;" : "=r"(pk) : "f"(0.f), "f"(v));
    return (uint16_t)(pk & 0xFFFFu);
}
#define CPA16(dst, src) asm volatile("cp.async.cg.shared.global [%0], [%1], 16;" :: "r"(dst), "l"(src))
#define CPA_COMMIT()    asm volatile("cp.async.commit_group;")
#define CPA_WAIT1()     asm volatile("cp.async.wait_group 1;")
#define CPA_WAIT0()     asm volatile("cp.async.wait_group 0;")

// ---------------- pack weights -> bf16, bias, zero xmean ----------------
__global__ void pack_kernel(const float* __restrict__ wq, const float* __restrict__ bq,
                            const float* __restrict__ wk, const float* __restrict__ bk,
                            const float* __restrict__ wv, const float* __restrict__ bv,
                            const float* __restrict__ wm, const float* __restrict__ bm) {
    int i  = blockIdx.x*blockDim.x + threadIdx.x;
    int nt = gridDim.x*blockDim.x;
    for (int idx = i; idx < FPAD*CH; idx += nt) {
        int f = idx >> 8, c = idx & 255;
        float v = 0.f;
        if      (f < 32)  v = wq[f*CH + c] * LOG2E;
        else if (f < 64)  v = wk[(f-32)*CH + c];
        else if (f < 320) v = wv[(f-64)*CH + c];
        else if (f == 320) v = wm[c];
        g_Wb[idx] = f2bf(v);
    }
    if (i < FPAD) {
        float bia = 0.f;
        if (i >= 64 && i < 320) bia = bv[i-64];
        else if (i == 320)      bia = bm[0];
        g_bias[i] = bia;
    }
    if (i < BATCH*CH) g_xmean[i] = 0.f;
}

// ---------------- x -> bf16 transpose [b][n][c] + channel sums ----------------
__global__ void __launch_bounds__(256) xconv_kernel(const float* __restrict__ x) {
    __shared__ float sm[64][133];
    __shared__ float msum[64];
    int nt = blockIdx.x, ct = blockIdx.y, b = blockIdx.z;
    int n0 = nt*128, c0 = ct*64;
    int t = threadIdx.x;
    if (t < 64) msum[t] = 0.f;
    __syncthreads();
    #pragma unroll
    for (int r = 0; r < 8; r++) {
        int idx = t + r*256;
        int ci = idx >> 5, n4 = idx & 31;
        float4 v = *(const float4*)&x[((size_t)(b*CH + c0 + ci))*NPIX + n0 + n4*4];
        sm[ci][n4*4+0]=v.x; sm[ci][n4*4+1]=v.y; sm[ci][n4*4+2]=v.z; sm[ci][n4*4+3]=v.w;
        atomicAdd(&msum[ci], (v.x+v.y)+(v.z+v.w));
    }
    __syncthreads();
    if (t < 64) atomicAdd(&g_xmean[b*CH + c0 + t], msum[t]);
    #pragma unroll
    for (int r = 0; r < 4; r++) {
        int idx = t + r*256;
        int ni = idx >> 3, ch = idx & 7;
        uint32_t p[4];
        #pragma unroll
        for (int e = 0; e < 4; e++) {
            float lo = sm[ch*8 + 2*e][ni], hi = sm[ch*8 + 2*e + 1][ni];
            asm("cvt.rn.bf16x2.f32 %0, %1, %2;" : "=r"(p[e]) : "f"(hi), "f"(lo));
        }
        uint4 o; o.x=p[0]; o.y=p[1]; o.z=p[2]; o.w=p[3];
        *(uint4*)(g_Xt + ((size_t)b*NPIX + n0 + ni)*CH + c0 + ch*8) = o;
    }
}

// ---------------- cbias[b][f] = -W[f].xmean[b]  (q/k centering) ----------------
__global__ void cbias_kernel() {
    int b = blockIdx.x, f = threadIdx.x;   // 64 threads
    float s = 0.f;
    for (int c = 0; c < CH; c++) {
        uint32_t u = (uint32_t)g_Wb[f*CH + c] << 16;
        s += __uint_as_float(u) * g_xmean[b*CH + c];
    }
    g_cbias[b*64 + f] = -s * (1.f/NPIX);
}

// ---------------- bf16 tensor-core GEMM: Y = W @ x^T ----------------
// CTA: 128 f x 128 n, K=256 single-shot. 8 warps = 4(m) x 2(n), warp 32f x 64n.
#define GEMM_SMEM 131072
__global__ void __launch_bounds__(256, 1) gemm2_kernel() {
    extern __shared__ __align__(128) char gsm[];
    uint32_t sb = smem_u32(gsm);
    int t = threadIdx.x, w = t >> 5, lane = t & 31;
    int nt = blockIdx.x, ft = blockIdx.y, b = blockIdx.z;
    int n0 = nt*128, fbase0 = ft*128;

    const uint16_t* Wsrc = g_Wb + (size_t)fbase0*CH;
    #pragma unroll
    for (int r = 0; r < 16; r++) {             // A: 128 f rows x 512B swizzled
        int idx = t + r*256;
        int f = idx >> 5, j = idx & 31;
        CPA16(sb + f*512 + ((j*16) ^ ((f & 7) << 4)), (const char*)(Wsrc + f*CH + j*8));
    }
    const uint16_t* Xsrc = g_Xt + ((size_t)b*NPIX + n0)*CH;
    #pragma unroll
    for (int r = 0; r < 16; r++) {             // B: 128 n rows x 512B swizzled
        int idx = t + r*256;
        int n = idx >> 5, j = idx & 31;
        CPA16(sb + 65536 + n*512 + ((j*16) ^ ((n & 7) << 4)), (const char*)(Xsrc + n*CH + j*8));
    }
    CPA_COMMIT(); CPA_WAIT0();
    __syncthreads();

    int wm = w >> 1, wn = w & 1;
    uint32_t abase = sb + (wm*32)*512;
    uint32_t bbase = sb + 65536 + (wn*64)*512;
    uint32_t arow = (uint32_t)(lane & 15), acsel = (uint32_t)((lane >> 4)*16);
    uint32_t axor = (uint32_t)((lane & 7) << 4);
    int lq = lane >> 3, lr = lane & 7;
    uint32_t lrow = (uint32_t)((lq >> 1)*8 + lr), lcsel = (uint32_t)((lq & 1)*16);
    uint32_t bxor = (uint32_t)(lr << 4);

    float acc[16][4];
    #pragma unroll
    for (int i = 0; i < 16; i++)
        #pragma unroll
        for (int j = 0; j < 4; j++) acc[i][j] = 0.f;

    #pragma unroll
    for (int k = 0; k < 16; k++) {
        uint32_t a0[4], a1[4];
        ldsm4(a0, abase + arow*512        + (((uint32_t)k*32 + acsel) ^ axor));
        ldsm4(a1, abase + (16+arow)*512   + (((uint32_t)k*32 + acsel) ^ axor));
        #pragma unroll
        for (int p = 0; p < 4; p++) {
            uint32_t bb[4];
            ldsm4(bb, bbase + (p*16 + lrow)*512 + (((uint32_t)k*32 + lcsel) ^ bxor));
            mma16816(acc[2*p],     a0, bb[0], bb[1]);
            mma16816(acc[2*p + 1], a0, bb[2], bb[3]);
            mma16816(acc[8 + 2*p],     a1, bb[0], bb[1]);
            mma16816(acc[8 + 2*p + 1], a1, bb[2], bb[3]);
        }
    }

    // epilogue: q/k fp32 -> g_Y, v relu+bf16 -> g_Vb, pm fp32 -> g_Y row 320
    int rr = lane >> 2, cc2 = 2*(lane & 3);
    #pragma unroll
    for (int mi = 0; mi < 2; mi++) {
        #pragma unroll
        for (int half = 0; half < 2; half++) {
            int f = fbase0 + wm*32 + mi*16 + rr + half*8;
            float bia = (f < 64) ? g_cbias[b*64 + f] : g_bias[f];
            bool isv = (f >= 64) && (f < 320);
            bool isy = (f < 64) || (f == 320);
            #pragma unroll
            for (int nj = 0; nj < 8; nj++) {
                float v0 = acc[mi*8 + nj][half*2 + 0] + bia;
                float v1 = acc[mi*8 + nj][half*2 + 1] + bia;
                int n = n0 + wn*64 + nj*8 + cc2;
                if (isv) {
                    v0 = fmaxf(v0, 0.f); v1 = fmaxf(v1, 0.f);
                    uint32_t pk;
                    asm("cvt.rn.bf16x2.f32 %0, %1, %2;" : "=r"(pk) : "f"(v1), "f"(v0));
                    *(uint32_t*)(g_Vb + ((size_t)b*CH + (f - 64))*NPIX + n) = pk;
                } else if (isy) {
                    float* yp = g_Y + ((size_t)b*FTOT + f)*NPIX + n;
                    yp[0] = v0; yp[1] = v1;
                }
            }
        }
    }
}

// ---------------- pm softmax (row 320), 1024 threads, single load pass ----------------
__global__ void __launch_bounds__(1024) masksoftmax_kernel() {
    int b = blockIdx.x, t = threadIdx.x;
    float* row = g_Y + ((size_t)b*FTOT + 320)*NPIX;
    __shared__ float red[32];
    float4 v = ((const float4*)row)[t];
    float e0 = __expf(v.x), e1 = __expf(v.y), e2 = __expf(v.z), e3 = __expf(v.w);
    float s = (e0 + e1) + (e2 + e3);
    #pragma unroll
    for (int o = 16; o > 0; o >>= 1) s += __shfl_xor_sync(0xffffffffu, s, o);
    if ((t & 31) == 0) red[t >> 5] = s;
    __syncthreads();
    if (t < 32) {
        float v2 = red[t];
        #pragma unroll
        for (int o = 16; o > 0; o >>= 1) v2 += __shfl_xor_sync(0xffffffffu, v2, o);
        if (t == 0) red[0] = v2;
    }
    __syncthreads();
    float inv = 1.f / red[0];
    float4 o; o.x = e0*inv; o.y = e1*inv; o.z = e2*inv; o.w = e3*inv;
    ((float4*)row)[t] = o;
}

// ---------------- vmask[b,c] = sum_n vbf16[b,c,n]*mask[b,n] ----------------
__global__ void __launch_bounds__(128) vmask_kernel() {
    int c = blockIdx.x, b = blockIdx.y, t = threadIdx.x;
    const uint4* vrow = (const uint4*)(g_Vb + ((size_t)b*CH + c)*NPIX);
    const float4* mrow = (const float4*)(g_Y + ((size_t)b*FTOT + 320)*NPIX);
    __shared__ float red[4];
    float s = 0.f;
    #pragma unroll
    for (int r = 0; r < 4; r++) {
        int idx = t + r*128;             // 512 chunks of 8 elems
        uint4 vv = vrow[idx];
        float4 m0 = mrow[idx*2], m1 = mrow[idx*2 + 1];
        s += bflo(vv.x)*m0.x + bfhi(vv.x)*m0.y + bflo(vv.y)*m0.z + bfhi(vv.y)*m0.w;
        s += bflo(vv.z)*m1.x + bfhi(vv.z)*m1.y + bflo(vv.w)*m1.z + bfhi(vv.w)*m1.w;
    }
    #pragma unroll
    for (int o = 16; o > 0; o >>= 1) s += __shfl_xor_sync(0xffffffffu, s, o);
    if ((t & 31) == 0) red[t >> 5] = s;
    __syncthreads();
    if (t == 0) g_vmask[b*CH + c] = (red[0] + red[1]) + (red[2] + red[3]);
}

// ---------------- q/k fp32 (centered) -> bf16 transposed [n][d] ----------------
__global__ void __launch_bounds__(256) qkconv_kernel() {
    __shared__ float sm[32][132];
    int n0 = blockIdx.x*128;
    int isk = blockIdx.y;
    int b = blockIdx.z;
    int t = threadIdx.x;
    const float* Yq = g_Y + ((size_t)b*FTOT + isk*32)*NPIX;
    #pragma unroll
    for (int r = 0; r < 4; r++) {
        int i = t + r*256;
        int d = i >> 5, c4 = i & 31;
        float4 v = *(const float4*)&Yq[(size_t)d*NPIX + n0 + c4*4];
        sm[d][c4*4+0]=v.x; sm[d][c4*4+1]=v.y; sm[d][c4*4+2]=v.z; sm[d][c4*4+3]=v.w;
    }
    __syncthreads();
    uint32_t* dst = (isk ? g_Kb : g_Qb) + ((size_t)b*NPIX + n0)*16;
    #pragma unroll
    for (int r = 0; r < 8; r++) {
        int i = t + r*256;
        int n = i >> 4, jp = i & 15;
        uint32_t pk;
        asm("cvt.rn.bf16x2.f32 %0, %1, %2;" : "=r"(pk) : "f"(sm[2*jp+1][n]), "f"(sm[2*jp][n]));
        dst[n*16 + jp] = pk;
    }
}

// ---------------- attention via mma.sync (HMMA) — unchanged from R5 ----------------
#define SM_VMK 0
#define SM_QS  1024
#define SM_KS0 9216
#define SM_KS1 17408
#define SM_VS0 25600
#define SM_VS1 91136
#define SM_TOTAL 156672

__global__ void __launch_bounds__(256, 1) attn_kernel(float* __restrict__ out) {
    extern __shared__ __align__(128) char smem[];
    uint32_t sb = smem_u32(smem);
    float* vmk = (float*)(smem + SM_VMK);
    int t = threadIdx.x, w = t >> 5, lane = t & 31;
    int b = blockIdx.y, m0 = blockIdx.x * 128;

    vmk[t] = g_vmask[b*CH + t];

    int lq = lane >> 3, lr = lane & 7;
    uint32_t lrow   = (uint32_t)((lq >> 1)*8 + lr);
    uint32_t lcsel  = (uint32_t)((lq & 1)*16);
    uint32_t arow   = (uint32_t)(lane & 15);
    uint32_t acsel  = (uint32_t)((lane >> 4)*16);
    uint32_t kxor   = (uint32_t)(((lr >> 1) & 3) << 4);
    uint32_t vxor   = (uint32_t)(lr << 4);

    #pragma unroll
    for (int kk = 0; kk < 2; kk++) {
        int idx = t + kk*256;
        int m = idx >> 2, j = idx & 3;
        const char* src = (const char*)(g_Qb + ((size_t)b*NPIX + m0 + m)*16 + j*4);
        uint32_t dst = sb + SM_QS + m*64 + ((j*16) ^ ((((uint32_t)m >> 1) & 3) << 4));
        CPA16(dst, src);
    }
    {
        uint32_t ksd = sb + SM_KS0, vsd = sb + SM_VS0;
        #pragma unroll
        for (int kk = 0; kk < 2; kk++) {
            int idx = t + kk*256;
            int n = idx >> 2, j = idx & 3;
            const char* src = (const char*)(g_Kb + ((size_t)b*NPIX + 0 + n)*16 + j*4);
            CPA16(ksd + n*64 + ((j*16) ^ ((((uint32_t)n >> 1) & 3) << 4)), src);
        }
        #pragma unroll
        for (int kk = 0; kk < 16; kk++) {
            int idx = t + kk*256;
            int c = idx >> 4, j = idx & 15;
            const char* src = (const char*)(g_Vb + ((size_t)b*CH + c)*NPIX + 0 + j*8);
            CPA16(vsd + c*256 + ((j*16) ^ (((uint32_t)c & 7) << 4)), src);
        }
    }
    CPA_COMMIT();

    float d2[32][4];
    #pragma unroll
    for (int i = 0; i < 32; i++)
        #pragma unroll
        for (int j = 0; j < 4; j++) d2[i][j] = 0.f;
    uint32_t aq[2][4];
    float den0 = 0.f, den1 = 0.f;

    #pragma unroll 1
    for (int i = 0; i < 32; i++) {
        if (i < 31) {
            int n0 = (i + 1) << 7;
            uint32_t ksd = sb + (((i + 1) & 1) ? SM_KS1 : SM_KS0);
            uint32_t vsd = sb + (((i + 1) & 1) ? SM_VS1 : SM_VS0);
            #pragma unroll
            for (int kk = 0; kk < 2; kk++) {
                int idx = t + kk*256;
                int n = idx >> 2, j = idx & 3;
                const char* src = (const char*)(g_Kb + ((size_t)b*NPIX + n0 + n)*16 + j*4);
                CPA16(ksd + n*64 + ((j*16) ^ ((((uint32_t)n >> 1) & 3) << 4)), src);
            }
            #pragma unroll
            for (int kk = 0; kk < 16; kk++) {
                int idx = t + kk*256;
                int c = idx >> 4, j = idx & 15;
                const char* src = (const char*)(g_Vb + ((size_t)b*CH + c)*NPIX + n0 + j*8);
                CPA16(vsd + c*256 + ((j*16) ^ (((uint32_t)c & 7) << 4)), src);
            }
        }
        CPA_COMMIT();
        CPA_WAIT1();
        __syncthreads();

        if (i == 0) {
            uint32_t qbase = sb + SM_QS + (w*16 + arow)*64;
            ldsm4(aq[0], qbase + ((0  + acsel) ^ kxor));
            ldsm4(aq[1], qbase + ((32 + acsel) ^ kxor));
        }

        uint32_t ksb = sb + ((i & 1) ? SM_KS1 : SM_KS0);
        uint32_t vsb = sb + ((i & 1) ? SM_VS1 : SM_VS0);

        #pragma unroll
        for (int h = 0; h < 8; h++) {
            float s0[4] = {0.f,0.f,0.f,0.f};
            float s1[4] = {0.f,0.f,0.f,0.f};
            uint32_t kb[4];
            uint32_t kbase = ksb + (h*16 + lrow)*64;
            ldsm4(kb, kbase + ((0 + lcsel) ^ kxor));
            mma16816(s0, aq[0], kb[0], kb[1]);
            mma16816(s1, aq[0], kb[2], kb[3]);
            ldsm4(kb, kbase + ((32 + lcsel) ^ kxor));
            mma16816(s0, aq[1], kb[0], kb[1]);
            mma16816(s1, aq[1], kb[2], kb[3]);
            float e00 = ex2f(s0[0]), e01 = ex2f(s0[1]), e02 = ex2f(s0[2]), e03 = ex2f(s0[3]);
            float e10 = ex2f(s1[0]), e11 = ex2f(s1[1]), e12 = ex2f(s1[2]), e13 = ex2f(s1[3]);
            den0 += (e00 + e01) + (e10 + e11);
            den1 += (e02 + e03) + (e12 + e13);
            uint32_t pk[4];
            asm("cvt.rn.bf16x2.f32 %0, %1, %2;" : "=r"(pk[0]) : "f"(e01), "f"(e00));
            asm("cvt.rn.bf16x2.f32 %0, %1, %2;" : "=r"(pk[1]) : "f"(e03), "f"(e02));
            asm("cvt.rn.bf16x2.f32 %0, %1, %2;" : "=r"(pk[2]) : "f"(e11), "f"(e10));
            asm("cvt.rn.bf16x2.f32 %0, %1, %2;" : "=r"(pk[3]) : "f"(e13), "f"(e12));

            uint32_t coloff = (uint32_t)(h*32 + lcsel);
            #pragma unroll
            for (int c16 = 0; c16 < 16; c16++) {
                uint32_t vb[4];
                ldsm4(vb, vsb + (c16*16 + lrow)*256 + (coloff ^ vxor));
                mma16816(d2[c16*2],     pk, vb[0], vb[1]);
                mma16816(d2[c16*2 + 1], pk, vb[2], vb[3]);
            }
        }
        __syncthreads();
    }

    float rs0 = den0, rs1 = den1;
    rs0 += __shfl_xor_sync(0xffffffffu, rs0, 1);
    rs0 += __shfl_xor_sync(0xffffffffu, rs0, 2);
    rs1 += __shfl_xor_sync(0xffffffffu, rs1, 1);
    rs1 += __shfl_xor_sync(0xffffffffu, rs1, 2);
    float i0 = 1.f / rs0, i1 = 1.f / rs1;

    int mlo = m0 + w*16 + (lane >> 2);
    int cb  = 2*(lane & 3);
    float* outb = out + OUTOFF + (size_t)b*CH*NPIX;
    #pragma unroll
    for (int cc = 0; cc < 32; cc++) {
        int c0 = cc*8 + cb;
        outb[(size_t)c0*NPIX + mlo]           = d2[cc][0]*i0 + vmk[c0];
        outb[(size_t)(c0+1)*NPIX + mlo]       = d2[cc][1]*i0 + vmk[c0+1];
        outb[(size_t)c0*NPIX + mlo + 8]       = d2[cc][2]*i1 + vmk[c0];
        outb[(size_t)(c0+1)*NPIX + mlo + 8]   = d2[cc][3]*i1 + vmk[c0+1];
    }
}

// ---------------- launch ----------------
extern "C" void kernel_launch(void* const* d_in, const int* in_sizes, int n_in,
                              void* d_out, int out_size) {
    const float* x  = (const float*)d_in[0];
    const float* wq = (const float*)d_in[1];
    const float* bq = (const float*)d_in[2];
    const float* wk = (const float*)d_in[3];
    const float* bk = (const float*)d_in[4];
    const float* wv = (const float*)d_in[5];
    const float* bv = (const float*)d_in[6];
    const float* wm = (const float*)d_in[7];
    const float* bm = (const float*)d_in[8];
    float* out = (float*)d_out;
    (void)bq; (void)bk;   // q/k biases cancel under spatial centering

    cudaFuncSetAttribute(attn_kernel,  cudaFuncAttributeMaxDynamicSharedMemorySize, SM_TOTAL);
    cudaFuncSetAttribute(gemm2_kernel, cudaFuncAttributeMaxDynamicSharedMemorySize, GEMM_SMEM);

    cudaMemcpyAsync(out, x, OUTOFF*sizeof(float), cudaMemcpyDeviceToDevice, 0);

    pack_kernel<<<128, 256>>>(wq, bq, wk, bk, wv, bv, wm, bm);
    xconv_kernel<<<dim3(NPIX/128, CH/64, BATCH), 256>>>(x);
    cbias_kernel<<<BATCH, 64>>>();
    gemm2_kernel<<<dim3(NPIX/128, 3, BATCH), 256, GEMM_SMEM>>>();
    masksoftmax_kernel<<<BATCH, 1024>>>();
    vmask_kernel<<<dim3(CH, BATCH), 128>>>();
    qkconv_kernel<<<dim3(NPIX/128, 2, BATCH), 256>>>();
    attn_kernel<<<dim3(NPIX/128, BATCH), 256, SM_TOTAL>>>(out);
}

// round 8
// speedup vs baseline: 6.7892x; 1.0229x over previous
#include <cuda_runtime.h>
#include <cstdint>

#define BATCH 4
#define CH    256
#define NPIX  4096
#define FTOT  321
#define FPAD  384
#define OUTOFF ((size_t)BATCH*CH*NPIX)
#define LOG2E 1.4426950408889634f

// ---------------- device scratch ----------------
__device__ __align__(16) uint16_t g_Wb[FPAD*CH];                 // bf16 packed weights [f][c] (q rows pre-scaled log2e)
__device__ float g_bias[FPAD];
__device__ float g_xmean[BATCH*CH];
__device__ float g_cbias[BATCH*64];
__device__ __align__(16) uint16_t g_Xt[(size_t)BATCH*NPIX*CH];   // bf16 x^T [b][n][c]
__device__ float g_Y[(size_t)BATCH*FTOT*NPIX];                   // fp32 (rows 0..63 q/k + row 320 pm)
__device__ float g_vmask[BATCH*CH];
__device__ __align__(16) uint32_t g_Qb[(size_t)BATCH*NPIX*16];
__device__ __align__(16) uint32_t g_Kb[(size_t)BATCH*NPIX*16];
__device__ __align__(16) uint16_t g_Vb[(size_t)BATCH*CH*NPIX];   // bf16 [b][c][n]

// ---------------- helpers ----------------
__device__ __forceinline__ uint32_t smem_u32(const void* p) {
    uint32_t a;
    asm("{ .reg .u64 t; cvta.to.shared.u64 t, %1; cvt.u32.u64 %0, t; }" : "=r"(a) : "l"(p));
    return a;
}
__device__ __forceinline__ void ldsm4(uint32_t* r, uint32_t addr) {
    asm volatile("ldmatrix.sync.aligned.m8n8.x4.shared.b16 {%0,%1,%2,%3}, [%4];"
        : "=r"(r[0]), "=r"(r[1]), "=r"(r[2]), "=r"(r[3]) : "r"(addr));
}
__device__ __forceinline__ void mma16816(float* c, const uint32_t* a, uint32_t b0, uint32_t b1) {
    asm volatile("mma.sync.aligned.m16n8k16.row.col.f32.bf16.bf16.f32 "
        "{%0,%1,%2,%3}, {%4,%5,%6,%7}, {%8,%9}, {%0,%1,%2,%3};"
        : "+f"(c[0]), "+f"(c[1]), "+f"(c[2]), "+f"(c[3])
        : "r"(a[0]), "r"(a[1]), "r"(a[2]), "r"(a[3]), "r"(b0), "r"(b1));
}
__device__ __forceinline__ float ex2f(float x) {
    float r; asm("ex2.approx.f32 %0, %1;" : "=f"(r) : "f"(x)); return r;
}
__device__ __forceinline__ float bflo(uint32_t u) { return __uint_as_float(u << 16); }
__device__ __forceinline__ float bfhi(uint32_t u) { return __uint_as_float(u & 0xFFFF0000u); }
__device__ __forceinline__ uint16_t f2bf(float v) {
    uint32_t pk;
    asm("cvt.rn.bf16x2.f32 %0, %1, %2;" : "=r"(pk) : "f"(0.f), "f"(v));
    return (uint16_t)(pk & 0xFFFFu);
}
#define CPA16(dst, src) asm volatile("cp.async.cg.shared.global [%0], [%1], 16;" :: "r"(dst), "l"(src))
#define CPA_COMMIT()    asm volatile("cp.async.commit_group;")
#define CPA_WAIT1()     asm volatile("cp.async.wait_group 1;")
#define CPA_WAIT0()     asm volatile("cp.async.wait_group 0;")

// ---------------- pack weights -> bf16, bias, zero xmean ----------------
__global__ void pack_kernel(const float* __restrict__ wq, const float* __restrict__ bq,
                            const float* __restrict__ wk, const float* __restrict__ bk,
                            const float* __restrict__ wv, const float* __restrict__ bv,
                            const float* __restrict__ wm, const float* __restrict__ bm) {
    int i  = blockIdx.x*blockDim.x + threadIdx.x;
    int nt = gridDim.x*blockDim.x;
    for (int idx = i; idx < FPAD*CH; idx += nt) {
        int f = idx >> 8, c = idx & 255;
        float v = 0.f;
        if      (f < 32)  v = wq[f*CH + c] * LOG2E;
        else if (f < 64)  v = wk[(f-32)*CH + c];
        else if (f < 320) v = wv[(f-64)*CH + c];
        else if (f == 320) v = wm[c];
        g_Wb[idx] = f2bf(v);
    }
    if (i < FPAD) {
        float bia = 0.f;
        if (i >= 64 && i < 320) bia = bv[i-64];
        else if (i == 320)      bia = bm[0];
        g_bias[i] = bia;
    }
    if (i < BATCH*CH) g_xmean[i] = 0.f;
}

// ---------------- x -> bf16 transpose [b][n][c] + channel sums + copy x->out ----------------
__global__ void __launch_bounds__(256) xconv_kernel(const float* __restrict__ x, float* __restrict__ out) {
    __shared__ float sm[64][133];
    __shared__ float msum[64];
    int nt = blockIdx.x, ct = blockIdx.y, b = blockIdx.z;
    int n0 = nt*128, c0 = ct*64;
    int t = threadIdx.x;
    if (t < 64) msum[t] = 0.f;
    __syncthreads();
    #pragma unroll
    for (int r = 0; r < 8; r++) {
        int idx = t + r*256;
        int ci = idx >> 5, n4 = idx & 31;
        size_t off = ((size_t)(b*CH + c0 + ci))*NPIX + n0 + n4*4;
        float4 v = *(const float4*)&x[off];
        *(float4*)&out[off] = v;                       // fused x copy (out half 0)
        sm[ci][n4*4+0]=v.x; sm[ci][n4*4+1]=v.y; sm[ci][n4*4+2]=v.z; sm[ci][n4*4+3]=v.w;
        atomicAdd(&msum[ci], (v.x+v.y)+(v.z+v.w));
    }
    __syncthreads();
    if (t < 64) atomicAdd(&g_xmean[b*CH + c0 + t], msum[t]);
    #pragma unroll
    for (int r = 0; r < 4; r++) {
        int idx = t + r*256;
        int ni = idx >> 3, ch = idx & 7;
        uint32_t p[4];
        #pragma unroll
        for (int e = 0; e < 4; e++) {
            float lo = sm[ch*8 + 2*e][ni], hi = sm[ch*8 + 2*e + 1][ni];
            asm("cvt.rn.bf16x2.f32 %0, %1, %2;" : "=r"(p[e]) : "f"(hi), "f"(lo));
        }
        uint4 o; o.x=p[0]; o.y=p[1]; o.z=p[2]; o.w=p[3];
        *(uint4*)(g_Xt + ((size_t)b*NPIX + n0 + ni)*CH + c0 + ch*8) = o;
    }
}

// ---------------- cbias[b][f] = -W[f].xmean[b] ----------------
__global__ void cbias_kernel() {
    int b = blockIdx.x, f = threadIdx.x;   // 64 threads
    float s = 0.f;
    for (int c = 0; c < CH; c++) {
        uint32_t u = (uint32_t)g_Wb[f*CH + c] << 16;
        s += __uint_as_float(u) * g_xmean[b*CH + c];
    }
    g_cbias[b*64 + f] = -s * (1.f/NPIX);
}

// ---------------- bf16 tensor-core GEMM: Y = W @ x^T, K-chunk pipelined ----------------
// CTA: 128 f x 64 n; K=256 in two 128-chunks, double-buffered. 8 warps = 4(f) x 2(n), warp 32f x 32n.
#define GSTAGE 49152                         // 32KB A + 16KB B per stage
#define GEMM_SMEM (2*GSTAGE)                 // 96KB -> 2 CTAs/SM
__global__ void __launch_bounds__(256, 2) gemm2_kernel() {
    extern __shared__ __align__(128) char gsm[];
    uint32_t sb = smem_u32(gsm);
    int t = threadIdx.x, w = t >> 5, lane = t & 31;
    int nt = blockIdx.x, ft = blockIdx.y, b = blockIdx.z;
    int n0g = nt*64, fbase0 = ft*128;

    const uint16_t* Wsrc = g_Wb + (size_t)fbase0*CH;
    const uint16_t* Xsrc = g_Xt + ((size_t)b*NPIX + n0g)*CH;

    // issue both K-chunks as separate cp.async groups
    #pragma unroll
    for (int kc = 0; kc < 2; kc++) {
        uint32_t sA = sb + kc*GSTAGE, sB = sA + 32768;
        #pragma unroll
        for (int r = 0; r < 8; r++) {                  // A: 128 rows x 256B
            int idx = t + r*256;
            int f = idx >> 4, j = idx & 15;
            CPA16(sA + f*256 + ((j*16) ^ ((f & 7) << 4)), (const char*)(Wsrc + f*CH + kc*128 + j*8));
        }
        #pragma unroll
        for (int r = 0; r < 4; r++) {                  // B: 64 rows x 256B
            int idx = t + r*256;
            int n = idx >> 4, j = idx & 15;
            CPA16(sB + n*256 + ((j*16) ^ ((n & 7) << 4)), (const char*)(Xsrc + n*CH + kc*128 + j*8));
        }
        CPA_COMMIT();
    }

    int wm = w >> 1, wn = w & 1;
    uint32_t arow = (uint32_t)(lane & 15), acsel = (uint32_t)((lane >> 4)*16);
    uint32_t axor = (uint32_t)((lane & 7) << 4);
    int lq = lane >> 3, lr = lane & 7;
    uint32_t lrow = (uint32_t)((lq >> 1)*8 + lr), lcsel = (uint32_t)((lq & 1)*16);
    uint32_t bxor = (uint32_t)(lr << 4);

    float acc[2][4][4];
    #pragma unroll
    for (int mi = 0; mi < 2; mi++)
        #pragma unroll
        for (int nj = 0; nj < 4; nj++)
            #pragma unroll
            for (int e = 0; e < 4; e++) acc[mi][nj][e] = 0.f;

    #pragma unroll
    for (int kc = 0; kc < 2; kc++) {
        if (kc == 0) CPA_WAIT1(); else CPA_WAIT0();
        __syncthreads();
        uint32_t sA = sb + kc*GSTAGE, sB = sA + 32768;
        uint32_t aAdr0 = sA + (wm*32 + arow)*256;
        uint32_t aAdr1 = sA + (wm*32 + 16 + arow)*256;
        uint32_t bAdr0 = sB + (wn*32 + lrow)*256;
        uint32_t bAdr1 = sB + (wn*32 + 16 + lrow)*256;
        #pragma unroll
        for (int k = 0; k < 8; k++) {
            uint32_t off_a = (((uint32_t)k*32 + acsel) ^ axor);
            uint32_t off_b = (((uint32_t)k*32 + lcsel) ^ bxor);
            uint32_t a0[4], a1[4], b0[4], b1[4];
            ldsm4(a0, aAdr0 + off_a);
            ldsm4(a1, aAdr1 + off_a);
            ldsm4(b0, bAdr0 + off_b);
            ldsm4(b1, bAdr1 + off_b);
            mma16816(acc[0][0], a0, b0[0], b0[1]);
            mma16816(acc[0][1], a0, b0[2], b0[3]);
            mma16816(acc[0][2], a0, b1[0], b1[1]);
            mma16816(acc[0][3], a0, b1[2], b1[3]);
            mma16816(acc[1][0], a1, b0[0], b0[1]);
            mma16816(acc[1][1], a1, b0[2], b0[3]);
            mma16816(acc[1][2], a1, b1[0], b1[1]);
            mma16816(acc[1][3], a1, b1[2], b1[3]);
        }
        if (kc == 0) __syncthreads();   // not strictly needed (distinct buffers) but cheap ordering
    }

    // epilogue: q/k fp32 -> g_Y, v relu+bf16 -> g_Vb, pm fp32 -> g_Y row 320
    int rr = lane >> 2, cc2 = 2*(lane & 3);
    #pragma unroll
    for (int mi = 0; mi < 2; mi++) {
        #pragma unroll
        for (int half = 0; half < 2; half++) {
            int f = fbase0 + wm*32 + mi*16 + rr + half*8;
            float bia = (f < 64) ? g_cbias[b*64 + f] : g_bias[f];
            bool isv = (f >= 64) && (f < 320);
            bool isy = (f < 64) || (f == 320);
            #pragma unroll
            for (int nj = 0; nj < 4; nj++) {
                float v0 = acc[mi][nj][half*2 + 0] + bia;
                float v1 = acc[mi][nj][half*2 + 1] + bia;
                int n = n0g + wn*32 + nj*8 + cc2;
                if (isv) {
                    v0 = fmaxf(v0, 0.f); v1 = fmaxf(v1, 0.f);
                    uint32_t pk;
                    asm("cvt.rn.bf16x2.f32 %0, %1, %2;" : "=r"(pk) : "f"(v1), "f"(v0));
                    *(uint32_t*)(g_Vb + ((size_t)b*CH + (f - 64))*NPIX + n) = pk;
                } else if (isy) {
                    float* yp = g_Y + ((size_t)b*FTOT + f)*NPIX + n;
                    yp[0] = v0; yp[1] = v1;
                }
            }
        }
    }
}

// ---------------- pm softmax (row 320) ----------------
__global__ void __launch_bounds__(1024) masksoftmax_kernel() {
    int b = blockIdx.x, t = threadIdx.x;
    float* row = g_Y + ((size_t)b*FTOT + 320)*NPIX;
    __shared__ float red[32];
    float4 v = ((const float4*)row)[t];
    float e0 = __expf(v.x), e1 = __expf(v.y), e2 = __expf(v.z), e3 = __expf(v.w);
    float s = (e0 + e1) + (e2 + e3);
    #pragma unroll
    for (int o = 16; o > 0; o >>= 1) s += __shfl_xor_sync(0xffffffffu, s, o);
    if ((t & 31) == 0) red[t >> 5] = s;
    __syncthreads();
    if (t < 32) {
        float v2 = red[t];
        #pragma unroll
        for (int o = 16; o > 0; o >>= 1) v2 += __shfl_xor_sync(0xffffffffu, v2, o);
        if (t == 0) red[0] = v2;
    }
    __syncthreads();
    float inv = 1.f / red[0];
    float4 o; o.x = e0*inv; o.y = e1*inv; o.z = e2*inv; o.w = e3*inv;
    ((float4*)row)[t] = o;
}

// ---------------- vmask ----------------
__global__ void __launch_bounds__(128) vmask_kernel() {
    int c = blockIdx.x, b = blockIdx.y, t = threadIdx.x;
    const uint4* vrow = (const uint4*)(g_Vb + ((size_t)b*CH + c)*NPIX);
    const float4* mrow = (const float4*)(g_Y + ((size_t)b*FTOT + 320)*NPIX);
    __shared__ float red[4];
    float s = 0.f;
    #pragma unroll
    for (int r = 0; r < 4; r++) {
        int idx = t + r*128;
        uint4 vv = vrow[idx];
        float4 m0 = mrow[idx*2], m1 = mrow[idx*2 + 1];
        s += bflo(vv.x)*m0.x + bfhi(vv.x)*m0.y + bflo(vv.y)*m0.z + bfhi(vv.y)*m0.w;
        s += bflo(vv.z)*m1.x + bfhi(vv.z)*m1.y + bflo(vv.w)*m1.z + bfhi(vv.w)*m1.w;
    }
    #pragma unroll
    for (int o = 16; o > 0; o >>= 1) s += __shfl_xor_sync(0xffffffffu, s, o);
    if ((t & 31) == 0) red[t >> 5] = s;
    __syncthreads();
    if (t == 0) g_vmask[b*CH + c] = (red[0] + red[1]) + (red[2] + red[3]);
}

// ---------------- q/k fp32 (centered via cbias) -> bf16 transposed [n][d] ----------------
__global__ void __launch_bounds__(256) qkconv_kernel() {
    __shared__ float sm[32][132];
    int n0 = blockIdx.x*128;
    int isk = blockIdx.y;
    int b = blockIdx.z;
    int t = threadIdx.x;
    const float* Yq = g_Y + ((size_t)b*FTOT + isk*32)*NPIX;
    #pragma unroll
    for (int r = 0; r < 4; r++) {
        int i = t + r*256;
        int d = i >> 5, c4 = i & 31;
        float4 v = *(const float4*)&Yq[(size_t)d*NPIX + n0 + c4*4];
        sm[d][c4*4+0]=v.x; sm[d][c4*4+1]=v.y; sm[d][c4*4+2]=v.z; sm[d][c4*4+3]=v.w;
    }
    __syncthreads();
    uint32_t* dst = (isk ? g_Kb : g_Qb) + ((size_t)b*NPIX + n0)*16;
    #pragma unroll
    for (int r = 0; r < 8; r++) {
        int i = t + r*256;
        int n = i >> 4, jp = i & 15;
        uint32_t pk;
        asm("cvt.rn.bf16x2.f32 %0, %1, %2;" : "=r"(pk) : "f"(sm[2*jp+1][n]), "f"(sm[2*jp][n]));
        dst[n*16 + jp] = pk;
    }
}

// ---------------- attention via mma.sync (HMMA) — unchanged (control) ----------------
#define SM_VMK 0
#define SM_QS  1024
#define SM_KS0 9216
#define SM_KS1 17408
#define SM_VS0 25600
#define SM_VS1 91136
#define SM_TOTAL 156672

__global__ void __launch_bounds__(256, 1) attn_kernel(float* __restrict__ out) {
    extern __shared__ __align__(128) char smem[];
    uint32_t sb = smem_u32(smem);
    float* vmk = (float*)(smem + SM_VMK);
    int t = threadIdx.x, w = t >> 5, lane = t & 31;
    int b = blockIdx.y, m0 = blockIdx.x * 128;

    vmk[t] = g_vmask[b*CH + t];

    int lq = lane >> 3, lr = lane & 7;
    uint32_t lrow   = (uint32_t)((lq >> 1)*8 + lr);
    uint32_t lcsel  = (uint32_t)((lq & 1)*16);
    uint32_t arow   = (uint32_t)(lane & 15);
    uint32_t acsel  = (uint32_t)((lane >> 4)*16);
    uint32_t kxor   = (uint32_t)(((lr >> 1) & 3) << 4);
    uint32_t vxor   = (uint32_t)(lr << 4);

    #pragma unroll
    for (int kk = 0; kk < 2; kk++) {
        int idx = t + kk*256;
        int m = idx >> 2, j = idx & 3;
        const char* src = (const char*)(g_Qb + ((size_t)b*NPIX + m0 + m)*16 + j*4);
        uint32_t dst = sb + SM_QS + m*64 + ((j*16) ^ ((((uint32_t)m >> 1) & 3) << 4));
        CPA16(dst, src);
    }
    {
        uint32_t ksd = sb + SM_KS0, vsd = sb + SM_VS0;
        #pragma unroll
        for (int kk = 0; kk < 2; kk++) {
            int idx = t + kk*256;
            int n = idx >> 2, j = idx & 3;
            const char* src = (const char*)(g_Kb + ((size_t)b*NPIX + 0 + n)*16 + j*4);
            CPA16(ksd + n*64 + ((j*16) ^ ((((uint32_t)n >> 1) & 3) << 4)), src);
        }
        #pragma unroll
        for (int kk = 0; kk < 16; kk++) {
            int idx = t + kk*256;
            int c = idx >> 4, j = idx & 15;
            const char* src = (const char*)(g_Vb + ((size_t)b*CH + c)*NPIX + 0 + j*8);
            CPA16(vsd + c*256 + ((j*16) ^ (((uint32_t)c & 7) << 4)), src);
        }
    }
    CPA_COMMIT();

    float d2[32][4];
    #pragma unroll
    for (int i = 0; i < 32; i++)
        #pragma unroll
        for (int j = 0; j < 4; j++) d2[i][j] = 0.f;
    uint32_t aq[2][4];
    float den0 = 0.f, den1 = 0.f;

    #pragma unroll 1
    for (int i = 0; i < 32; i++) {
        if (i < 31) {
            int n0 = (i + 1) << 7;
            uint32_t ksd = sb + (((i + 1) & 1) ? SM_KS1 : SM_KS0);
            uint32_t vsd = sb + (((i + 1) & 1) ? SM_VS1 : SM_VS0);
            #pragma unroll
            for (int kk = 0; kk < 2; kk++) {
                int idx = t + kk*256;
                int n = idx >> 2, j = idx & 3;
                const char* src = (const char*)(g_Kb + ((size_t)b*NPIX + n0 + n)*16 + j*4);
                CPA16(ksd + n*64 + ((j*16) ^ ((((uint32_t)n >> 1) & 3) << 4)), src);
            }
            #pragma unroll
            for (int kk = 0; kk < 16; kk++) {
                int idx = t + kk*256;
                int c = idx >> 4, j = idx & 15;
                const char* src = (const char*)(g_Vb + ((size_t)b*CH + c)*NPIX + n0 + j*8);
                CPA16(vsd + c*256 + ((j*16) ^ (((uint32_t)c & 7) << 4)), src);
            }
        }
        CPA_COMMIT();
        CPA_WAIT1();
        __syncthreads();

        if (i == 0) {
            uint32_t qbase = sb + SM_QS + (w*16 + arow)*64;
            ldsm4(aq[0], qbase + ((0  + acsel) ^ kxor));
            ldsm4(aq[1], qbase + ((32 + acsel) ^ kxor));
        }

        uint32_t ksb = sb + ((i & 1) ? SM_KS1 : SM_KS0);
        uint32_t vsb = sb + ((i & 1) ? SM_VS1 : SM_VS0);

        #pragma unroll
        for (int h = 0; h < 8; h++) {
            float s0[4] = {0.f,0.f,0.f,0.f};
            float s1[4] = {0.f,0.f,0.f,0.f};
            uint32_t kb[4];
            uint32_t kbase = ksb + (h*16 + lrow)*64;
            ldsm4(kb, kbase + ((0 + lcsel) ^ kxor));
            mma16816(s0, aq[0], kb[0], kb[1]);
            mma16816(s1, aq[0], kb[2], kb[3]);
            ldsm4(kb, kbase + ((32 + lcsel) ^ kxor));
            mma16816(s0, aq[1], kb[0], kb[1]);
            mma16816(s1, aq[1], kb[2], kb[3]);
            float e00 = ex2f(s0[0]), e01 = ex2f(s0[1]), e02 = ex2f(s0[2]), e03 = ex2f(s0[3]);
            float e10 = ex2f(s1[0]), e11 = ex2f(s1[1]), e12 = ex2f(s1[2]), e13 = ex2f(s1[3]);
            den0 += (e00 + e01) + (e10 + e11);
            den1 += (e02 + e03) + (e12 + e13);
            uint32_t pk[4];
            asm("cvt.rn.bf16x2.f32 %0, %1, %2;" : "=r"(pk[0]) : "f"(e01), "f"(e00));
            asm("cvt.rn.bf16x2.f32 %0, %1, %2;" : "=r"(pk[1]) : "f"(e03), "f"(e02));
            asm("cvt.rn.bf16x2.f32 %0, %1, %2;" : "=r"(pk[2]) : "f"(e11), "f"(e10));
            asm("cvt.rn.bf16x2.f32 %0, %1, %2;" : "=r"(pk[3]) : "f"(e13), "f"(e12));

            uint32_t coloff = (uint32_t)(h*32 + lcsel);
            #pragma unroll
            for (int c16 = 0; c16 < 16; c16++) {
                uint32_t vb[4];
                ldsm4(vb, vsb + (c16*16 + lrow)*256 + (coloff ^ vxor));
                mma16816(d2[c16*2],     pk, vb[0], vb[1]);
                mma16816(d2[c16*2 + 1], pk, vb[2], vb[3]);
            }
        }
        __syncthreads();
    }

    float rs0 = den0, rs1 = den1;
    rs0 += __shfl_xor_sync(0xffffffffu, rs0, 1);
    rs0 += __shfl_xor_sync(0xffffffffu, rs0, 2);
    rs1 += __shfl_xor_sync(0xffffffffu, rs1, 1);
    rs1 += __shfl_xor_sync(0xffffffffu, rs1, 2);
    float i0 = 1.f / rs0, i1 = 1.f / rs1;

    int mlo = m0 + w*16 + (lane >> 2);
    int cb  = 2*(lane & 3);
    float* outb = out + OUTOFF + (size_t)b*CH*NPIX;
    #pragma unroll
    for (int cc = 0; cc < 32; cc++) {
        int c0 = cc*8 + cb;
        outb[(size_t)c0*NPIX + mlo]           = d2[cc][0]*i0 + vmk[c0];
        outb[(size_t)(c0+1)*NPIX + mlo]       = d2[cc][1]*i0 + vmk[c0+1];
        outb[(size_t)c0*NPIX + mlo + 8]       = d2[cc][2]*i1 + vmk[c0];
        outb[(size_t)(c0+1)*NPIX + mlo + 8]   = d2[cc][3]*i1 + vmk[c0+1];
    }
}

// ---------------- launch ----------------
extern "C" void kernel_launch(void* const* d_in, const int* in_sizes, int n_in,
                              void* d_out, int out_size) {
    const float* x  = (const float*)d_in[0];
    const float* wq = (const float*)d_in[1];
    const float* bq = (const float*)d_in[2];
    const float* wk = (const float*)d_in[3];
    const float* bk = (const float*)d_in[4];
    const float* wv = (const float*)d_in[5];
    const float* bv = (const float*)d_in[6];
    const float* wm = (const float*)d_in[7];
    const float* bm = (const float*)d_in[8];
    float* out = (float*)d_out;
    (void)bq; (void)bk;   // q/k biases cancel under spatial centering

    cudaFuncSetAttribute(attn_kernel,  cudaFuncAttributeMaxDynamicSharedMemorySize, SM_TOTAL);
    cudaFuncSetAttribute(gemm2_kernel, cudaFuncAttributeMaxDynamicSharedMemorySize, GEMM_SMEM);

    pack_kernel<<<128, 256>>>(wq, bq, wk, bk, wv, bv, wm, bm);
    xconv_kernel<<<dim3(NPIX/128, CH/64, BATCH), 256>>>(x, out);
    cbias_kernel<<<BATCH, 64>>>();
    gemm2_kernel<<<dim3(NPIX/64, 3, BATCH), 256, GEMM_SMEM>>>();
    masksoftmax_kernel<<<BATCH, 1024>>>();
    vmask_kernel<<<dim3(CH, BATCH), 128>>>();
    qkconv_kernel<<<dim3(NPIX/128, 2, BATCH), 256>>>();
    attn_kernel<<<dim3(NPIX/128, BATCH), 256, SM_TOTAL>>>(out);
}

// round 9
// speedup vs baseline: 7.5081x; 1.1059x over previous
#include <cuda_runtime.h>
#include <cuda_fp16.h>
#include <cstdint>

#define BATCH 4
#define CH    256
#define NPIX  4096
#define FTOT  321
#define FPAD  384
#define OUTOFF ((size_t)BATCH*CH*NPIX)
#define LOG2E 1.4426950408889634f
#define ONESH 0x3C003C00u

// ---------------- device scratch ----------------
__device__ __align__(16) uint16_t g_Wb[FPAD*CH];                 // fp16 packed weights [f][c] (q rows pre-scaled log2e)
__device__ float g_bias[FPAD];
__device__ float g_xmean[BATCH*CH];
__device__ float g_cbias[BATCH*64];
__device__ __align__(16) uint16_t g_Xt[(size_t)BATCH*NPIX*CH];   // fp16 x^T [b][n][c]
__device__ float g_Y[(size_t)BATCH*FTOT*NPIX];                   // fp32 (rows 0..63 q/k + row 320 pm)
__device__ float g_vmask[BATCH*CH];
__device__ __align__(16) uint32_t g_Qb[(size_t)BATCH*NPIX*16];   // fp16x2 [b][n][16]
__device__ __align__(16) uint32_t g_Kb[(size_t)BATCH*NPIX*16];
__device__ __align__(16) uint16_t g_Vb[(size_t)BATCH*CH*NPIX];   // fp16 [b][c][n]

// ---------------- helpers ----------------
__device__ __forceinline__ uint32_t smem_u32(const void* p) {
    uint32_t a;
    asm("{ .reg .u64 t; cvta.to.shared.u64 t, %1; cvt.u32.u64 %0, t; }" : "=r"(a) : "l"(p));
    return a;
}
__device__ __forceinline__ void ldsm4(uint32_t* r, uint32_t addr) {
    asm volatile("ldmatrix.sync.aligned.m8n8.x4.shared.b16 {%0,%1,%2,%3}, [%4];"
        : "=r"(r[0]), "=r"(r[1]), "=r"(r[2]), "=r"(r[3]) : "r"(addr));
}
__device__ __forceinline__ void mma16816(float* c, const uint32_t* a, uint32_t b0, uint32_t b1) {
    asm volatile("mma.sync.aligned.m16n8k16.row.col.f32.f16.f16.f32 "
        "{%0,%1,%2,%3}, {%4,%5,%6,%7}, {%8,%9}, {%0,%1,%2,%3};"
        : "+f"(c[0]), "+f"(c[1]), "+f"(c[2]), "+f"(c[3])
        : "r"(a[0]), "r"(a[1]), "r"(a[2]), "r"(a[3]), "r"(b0), "r"(b1));
}
__device__ __forceinline__ uint32_t h2pk(float lo, float hi) {
    __half2 h = __floats2half2_rn(lo, hi);
    return *(uint32_t*)&h;
}
__device__ __forceinline__ uint32_t hexp2pk(float lo, float hi) {
    __half2 h = h2exp2(__floats2half2_rn(lo, hi));
    return *(uint32_t*)&h;
}
#define CPA16(dst, src) asm volatile("cp.async.cg.shared.global [%0], [%1], 16;" :: "r"(dst), "l"(src))
#define CPA_COMMIT()    asm volatile("cp.async.commit_group;")
#define CPA_WAIT1()     asm volatile("cp.async.wait_group 1;")
#define CPA_WAIT0()     asm volatile("cp.async.wait_group 0;")

// ---------------- pack weights -> fp16, bias, zero xmean ----------------
__global__ void pack_kernel(const float* __restrict__ wq, const float* __restrict__ bq,
                            const float* __restrict__ wk, const float* __restrict__ bk,
                            const float* __restrict__ wv, const float* __restrict__ bv,
                            const float* __restrict__ wm, const float* __restrict__ bm) {
    int i  = blockIdx.x*blockDim.x + threadIdx.x;
    int nt = gridDim.x*blockDim.x;
    for (int idx = i; idx < FPAD*CH; idx += nt) {
        int f = idx >> 8, c = idx & 255;
        float v = 0.f;
        if      (f < 32)  v = wq[f*CH + c] * LOG2E;
        else if (f < 64)  v = wk[(f-32)*CH + c];
        else if (f < 320) v = wv[(f-64)*CH + c];
        else if (f == 320) v = wm[c];
        g_Wb[idx] = __half_as_ushort(__float2half_rn(v));
    }
    if (i < FPAD) {
        float bia = 0.f;
        if (i >= 64 && i < 320) bia = bv[i-64];
        else if (i == 320)      bia = bm[0];
        g_bias[i] = bia;
    }
    if (i < BATCH*CH) g_xmean[i] = 0.f;
}

// ---------------- x -> fp16 transpose [b][n][c] + channel sums + copy x->out ----------------
__global__ void __launch_bounds__(256) xconv_kernel(const float* __restrict__ x, float* __restrict__ out) {
    __shared__ float sm[64][133];
    __shared__ float msum[64];
    int nt = blockIdx.x, ct = blockIdx.y, b = blockIdx.z;
    int n0 = nt*128, c0 = ct*64;
    int t = threadIdx.x;
    if (t < 64) msum[t] = 0.f;
    __syncthreads();
    #pragma unroll
    for (int r = 0; r < 8; r++) {
        int idx = t + r*256;
        int ci = idx >> 5, n4 = idx & 31;
        size_t off = ((size_t)(b*CH + c0 + ci))*NPIX + n0 + n4*4;
        float4 v = *(const float4*)&x[off];
        *(float4*)&out[off] = v;                       // fused x copy
        sm[ci][n4*4+0]=v.x; sm[ci][n4*4+1]=v.y; sm[ci][n4*4+2]=v.z; sm[ci][n4*4+3]=v.w;
        atomicAdd(&msum[ci], (v.x+v.y)+(v.z+v.w));
    }
    __syncthreads();
    if (t < 64) atomicAdd(&g_xmean[b*CH + c0 + t], msum[t]);
    #pragma unroll
    for (int r = 0; r < 4; r++) {
        int idx = t + r*256;
        int ni = idx >> 3, ch = idx & 7;
        uint32_t p[4];
        #pragma unroll
        for (int e = 0; e < 4; e++)
            p[e] = h2pk(sm[ch*8 + 2*e][ni], sm[ch*8 + 2*e + 1][ni]);
        uint4 o; o.x=p[0]; o.y=p[1]; o.z=p[2]; o.w=p[3];
        *(uint4*)(g_Xt + ((size_t)b*NPIX + n0 + ni)*CH + c0 + ch*8) = o;
    }
}

// ---------------- cbias[b][f] = -W[f].xmean[b] ----------------
__global__ void cbias_kernel() {
    int b = blockIdx.x, f = threadIdx.x;   // 64 threads
    float s = 0.f;
    for (int c = 0; c < CH; c++)
        s += __half2float(__ushort_as_half(g_Wb[f*CH + c])) * g_xmean[b*CH + c];
    g_cbias[b*64 + f] = -s * (1.f/NPIX);
}

// ---------------- fp16 tensor-core GEMM: Y = W @ x^T, K-chunk pipelined ----------------
#define GSTAGE 49152
#define GEMM_SMEM (2*GSTAGE)
__global__ void __launch_bounds__(256, 2) gemm2_kernel() {
    extern __shared__ __align__(128) char gsm[];
    uint32_t sb = smem_u32(gsm);
    int t = threadIdx.x, w = t >> 5, lane = t & 31;
    int nt = blockIdx.x, ft = blockIdx.y, b = blockIdx.z;
    int n0g = nt*64, fbase0 = ft*128;

    const uint16_t* Wsrc = g_Wb + (size_t)fbase0*CH;
    const uint16_t* Xsrc = g_Xt + ((size_t)b*NPIX + n0g)*CH;

    #pragma unroll
    for (int kc = 0; kc < 2; kc++) {
        uint32_t sA = sb + kc*GSTAGE, sB = sA + 32768;
        #pragma unroll
        for (int r = 0; r < 8; r++) {
            int idx = t + r*256;
            int f = idx >> 4, j = idx & 15;
            CPA16(sA + f*256 + ((j*16) ^ ((f & 7) << 4)), (const char*)(Wsrc + f*CH + kc*128 + j*8));
        }
        #pragma unroll
        for (int r = 0; r < 4; r++) {
            int idx = t + r*256;
            int n = idx >> 4, j = idx & 15;
            CPA16(sB + n*256 + ((j*16) ^ ((n & 7) << 4)), (const char*)(Xsrc + n*CH + kc*128 + j*8));
        }
        CPA_COMMIT();
    }

    int wm = w >> 1, wn = w & 1;
    uint32_t arow = (uint32_t)(lane & 15), acsel = (uint32_t)((lane >> 4)*16);
    uint32_t axor = (uint32_t)((lane & 7) << 4);
    int lq = lane >> 3, lr = lane & 7;
    uint32_t lrow = (uint32_t)((lq >> 1)*8 + lr), lcsel = (uint32_t)((lq & 1)*16);
    uint32_t bxor = (uint32_t)(lr << 4);

    float acc[2][4][4];
    #pragma unroll
    for (int mi = 0; mi < 2; mi++)
        #pragma unroll
        for (int nj = 0; nj < 4; nj++)
            #pragma unroll
            for (int e = 0; e < 4; e++) acc[mi][nj][e] = 0.f;

    #pragma unroll
    for (int kc = 0; kc < 2; kc++) {
        if (kc == 0) CPA_WAIT1(); else CPA_WAIT0();
        __syncthreads();
        uint32_t sA = sb + kc*GSTAGE, sB = sA + 32768;
        uint32_t aAdr0 = sA + (wm*32 + arow)*256;
        uint32_t aAdr1 = sA + (wm*32 + 16 + arow)*256;
        uint32_t bAdr0 = sB + (wn*32 + lrow)*256;
        uint32_t bAdr1 = sB + (wn*32 + 16 + lrow)*256;
        #pragma unroll
        for (int k = 0; k < 8; k++) {
            uint32_t off_a = (((uint32_t)k*32 + acsel) ^ axor);
            uint32_t off_b = (((uint32_t)k*32 + lcsel) ^ bxor);
            uint32_t a0[4], a1[4], b0[4], b1[4];
            ldsm4(a0, aAdr0 + off_a);
            ldsm4(a1, aAdr1 + off_a);
            ldsm4(b0, bAdr0 + off_b);
            ldsm4(b1, bAdr1 + off_b);
            mma16816(acc[0][0], a0, b0[0], b0[1]);
            mma16816(acc[0][1], a0, b0[2], b0[3]);
            mma16816(acc[0][2], a0, b1[0], b1[1]);
            mma16816(acc[0][3], a0, b1[2], b1[3]);
            mma16816(acc[1][0], a1, b0[0], b0[1]);
            mma16816(acc[1][1], a1, b0[2], b0[3]);
            mma16816(acc[1][2], a1, b1[0], b1[1]);
            mma16816(acc[1][3], a1, b1[2], b1[3]);
        }
        if (kc == 0) __syncthreads();
    }

    // epilogue: q/k fp32 -> g_Y, v relu+fp16 -> g_Vb, pm fp32 -> g_Y row 320
    int rr = lane >> 2, cc2 = 2*(lane & 3);
    #pragma unroll
    for (int mi = 0; mi < 2; mi++) {
        #pragma unroll
        for (int half = 0; half < 2; half++) {
            int f = fbase0 + wm*32 + mi*16 + rr + half*8;
            float bia = (f < 64) ? g_cbias[b*64 + f] : g_bias[f];
            bool isv = (f >= 64) && (f < 320);
            bool isy = (f < 64) || (f == 320);
            #pragma unroll
            for (int nj = 0; nj < 4; nj++) {
                float v0 = acc[mi][nj][half*2 + 0] + bia;
                float v1 = acc[mi][nj][half*2 + 1] + bia;
                int n = n0g + wn*32 + nj*8 + cc2;
                if (isv) {
                    v0 = fmaxf(v0, 0.f); v1 = fmaxf(v1, 0.f);
                    *(uint32_t*)(g_Vb + ((size_t)b*CH + (f - 64))*NPIX + n) = h2pk(v0, v1);
                } else if (isy) {
                    float* yp = g_Y + ((size_t)b*FTOT + f)*NPIX + n;
                    yp[0] = v0; yp[1] = v1;
                }
            }
        }
    }
}

// ---------------- pm softmax (row 320) ----------------
__global__ void __launch_bounds__(1024) masksoftmax_kernel() {
    int b = blockIdx.x, t = threadIdx.x;
    float* row = g_Y + ((size_t)b*FTOT + 320)*NPIX;
    __shared__ float red[32];
    float4 v = ((const float4*)row)[t];
    float e0 = __expf(v.x), e1 = __expf(v.y), e2 = __expf(v.z), e3 = __expf(v.w);
    float s = (e0 + e1) + (e2 + e3);
    #pragma unroll
    for (int o = 16; o > 0; o >>= 1) s += __shfl_xor_sync(0xffffffffu, s, o);
    if ((t & 31) == 0) red[t >> 5] = s;
    __syncthreads();
    if (t < 32) {
        float v2 = red[t];
        #pragma unroll
        for (int o = 16; o > 0; o >>= 1) v2 += __shfl_xor_sync(0xffffffffu, v2, o);
        if (t == 0) red[0] = v2;
    }
    __syncthreads();
    float inv = 1.f / red[0];
    float4 o; o.x = e0*inv; o.y = e1*inv; o.z = e2*inv; o.w = e3*inv;
    ((float4*)row)[t] = o;
}

// ---------------- vmask[b,c] = sum_n vfp16[b,c,n]*mask[b,n] ----------------
__global__ void __launch_bounds__(128) vmask_kernel() {
    int c = blockIdx.x, b = blockIdx.y, t = threadIdx.x;
    const uint4* vrow = (const uint4*)(g_Vb + ((size_t)b*CH + c)*NPIX);
    const float4* mrow = (const float4*)(g_Y + ((size_t)b*FTOT + 320)*NPIX);
    __shared__ float red[4];
    float s = 0.f;
    #pragma unroll
    for (int r = 0; r < 4; r++) {
        int idx = t + r*128;
        uint4 vv = vrow[idx];
        float4 m0 = mrow[idx*2], m1 = mrow[idx*2 + 1];
        float2 f0 = __half22float2(*(__half2*)&vv.x);
        float2 f1 = __half22float2(*(__half2*)&vv.y);
        float2 f2 = __half22float2(*(__half2*)&vv.z);
        float2 f3 = __half22float2(*(__half2*)&vv.w);
        s += f0.x*m0.x + f0.y*m0.y + f1.x*m0.z + f1.y*m0.w;
        s += f2.x*m1.x + f2.y*m1.y + f3.x*m1.z + f3.y*m1.w;
    }
    #pragma unroll
    for (int o = 16; o > 0; o >>= 1) s += __shfl_xor_sync(0xffffffffu, s, o);
    if ((t & 31) == 0) red[t >> 5] = s;
    __syncthreads();
    if (t == 0) g_vmask[b*CH + c] = (red[0] + red[1]) + (red[2] + red[3]);
}

// ---------------- q/k fp32 (centered via cbias) -> fp16 transposed [n][d] ----------------
__global__ void __launch_bounds__(256) qkconv_kernel() {
    __shared__ float sm[32][132];
    int n0 = blockIdx.x*128;
    int isk = blockIdx.y;
    int b = blockIdx.z;
    int t = threadIdx.x;
    const float* Yq = g_Y + ((size_t)b*FTOT + isk*32)*NPIX;
    #pragma unroll
    for (int r = 0; r < 4; r++) {
        int i = t + r*256;
        int d = i >> 5, c4 = i & 31;
        float4 v = *(const float4*)&Yq[(size_t)d*NPIX + n0 + c4*4];
        sm[d][c4*4+0]=v.x; sm[d][c4*4+1]=v.y; sm[d][c4*4+2]=v.z; sm[d][c4*4+3]=v.w;
    }
    __syncthreads();
    uint32_t* dst = (isk ? g_Kb : g_Qb) + ((size_t)b*NPIX + n0)*16;
    #pragma unroll
    for (int r = 0; r < 8; r++) {
        int i = t + r*256;
        int n = i >> 4, jp = i & 15;
        dst[n*16 + jp] = h2pk(sm[2*jp][n], sm[2*jp+1][n]);
    }
}

// ---------------- attention via mma.sync (f16) ----------------
#define SM_VMK 0
#define SM_QS  1024
#define SM_KS0 9216
#define SM_KS1 17408
#define SM_VS0 25600
#define SM_VS1 91136
#define SM_TOTAL 156672

__global__ void __launch_bounds__(256, 1) attn_kernel(float* __restrict__ out) {
    extern __shared__ __align__(128) char smem[];
    uint32_t sb = smem_u32(smem);
    float* vmk = (float*)(smem + SM_VMK);
    int t = threadIdx.x, w = t >> 5, lane = t & 31;
    int b = blockIdx.y, m0 = blockIdx.x * 128;

    vmk[t] = g_vmask[b*CH + t];

    int lq = lane >> 3, lr = lane & 7;
    uint32_t lrow   = (uint32_t)((lq >> 1)*8 + lr);
    uint32_t lcsel  = (uint32_t)((lq & 1)*16);
    uint32_t arow   = (uint32_t)(lane & 15);
    uint32_t acsel  = (uint32_t)((lane >> 4)*16);
    uint32_t kxor   = (uint32_t)(((lr >> 1) & 3) << 4);
    uint32_t vxor   = (uint32_t)(lr << 4);

    #pragma unroll
    for (int kk = 0; kk < 2; kk++) {
        int idx = t + kk*256;
        int m = idx >> 2, j = idx & 3;
        const char* src = (const char*)(g_Qb + ((size_t)b*NPIX + m0 + m)*16 + j*4);
        uint32_t dst = sb + SM_QS + m*64 + ((j*16) ^ ((((uint32_t)m >> 1) & 3) << 4));
        CPA16(dst, src);
    }
    {
        uint32_t ksd = sb + SM_KS0, vsd = sb + SM_VS0;
        #pragma unroll
        for (int kk = 0; kk < 2; kk++) {
            int idx = t + kk*256;
            int n = idx >> 2, j = idx & 3;
            const char* src = (const char*)(g_Kb + ((size_t)b*NPIX + 0 + n)*16 + j*4);
            CPA16(ksd + n*64 + ((j*16) ^ ((((uint32_t)n >> 1) & 3) << 4)), src);
        }
        #pragma unroll
        for (int kk = 0; kk < 16; kk++) {
            int idx = t + kk*256;
            int c = idx >> 4, j = idx & 15;
            const char* src = (const char*)(g_Vb + ((size_t)b*CH + c)*NPIX + 0 + j*8);
            CPA16(vsd + c*256 + ((j*16) ^ (((uint32_t)c & 7) << 4)), src);
        }
    }
    CPA_COMMIT();

    float d2[32][4];
    #pragma unroll
    for (int i = 0; i < 32; i++)
        #pragma unroll
        for (int j = 0; j < 4; j++) d2[i][j] = 0.f;
    float dden[4] = {0.f, 0.f, 0.f, 0.f};     // row-sum accumulator via ones-MMA
    uint32_t aq[2][4];

    #pragma unroll 1
    for (int i = 0; i < 32; i++) {
        if (i < 31) {
            int n0 = (i + 1) << 7;
            uint32_t ksd = sb + (((i + 1) & 1) ? SM_KS1 : SM_KS0);
            uint32_t vsd = sb + (((i + 1) & 1) ? SM_VS1 : SM_VS0);
            #pragma unroll
            for (int kk = 0; kk < 2; kk++) {
                int idx = t + kk*256;
                int n = idx >> 2, j = idx & 3;
                const char* src = (const char*)(g_Kb + ((size_t)b*NPIX + n0 + n)*16 + j*4);
                CPA16(ksd + n*64 + ((j*16) ^ ((((uint32_t)n >> 1) & 3) << 4)), src);
            }
            #pragma unroll
            for (int kk = 0; kk < 16; kk++) {
                int idx = t + kk*256;
                int c = idx >> 4, j = idx & 15;
                const char* src = (const char*)(g_Vb + ((size_t)b*CH + c)*NPIX + n0 + j*8);
                CPA16(vsd + c*256 + ((j*16) ^ (((uint32_t)c & 7) << 4)), src);
            }
        }
        CPA_COMMIT();
        CPA_WAIT1();
        __syncthreads();

        if (i == 0) {
            uint32_t qbase = sb + SM_QS + (w*16 + arow)*64;
            ldsm4(aq[0], qbase + ((0  + acsel) ^ kxor));
            ldsm4(aq[1], qbase + ((32 + acsel) ^ kxor));
        }

        uint32_t ksb = sb + ((i & 1) ? SM_KS1 : SM_KS0);
        uint32_t vsb = sb + ((i & 1) ? SM_VS1 : SM_VS0);

        #pragma unroll
        for (int h = 0; h < 8; h++) {
            float s0[4] = {0.f,0.f,0.f,0.f};
            float s1[4] = {0.f,0.f,0.f,0.f};
            uint32_t kb[4];
            uint32_t kbase = ksb + (h*16 + lrow)*64;
            ldsm4(kb, kbase + ((0 + lcsel) ^ kxor));
            mma16816(s0, aq[0], kb[0], kb[1]);
            mma16816(s1, aq[0], kb[2], kb[3]);
            ldsm4(kb, kbase + ((32 + lcsel) ^ kxor));
            mma16816(s0, aq[1], kb[0], kb[1]);
            mma16816(s1, aq[1], kb[2], kb[3]);

            // P = 2^S in fp16 pairs, directly in A-fragment layout
            uint32_t pk[4];
            pk[0] = hexp2pk(s0[0], s0[1]);
            pk[1] = hexp2pk(s0[2], s0[3]);
            pk[2] = hexp2pk(s1[0], s1[1]);
            pk[3] = hexp2pk(s1[2], s1[3]);

            mma16816(dden, pk, ONESH, ONESH);   // row sums (denominator) via tensor core

            uint32_t coloff = (uint32_t)(h*32 + lcsel);
            #pragma unroll
            for (int c16 = 0; c16 < 16; c16++) {
                uint32_t vb[4];
                ldsm4(vb, vsb + (c16*16 + lrow)*256 + (coloff ^ vxor));
                mma16816(d2[c16*2],     pk, vb[0], vb[1]);
                mma16816(d2[c16*2 + 1], pk, vb[2], vb[3]);
            }
        }
        __syncthreads();
    }

    float i0 = 1.f / dden[0];    // all 8 den columns equal; [0] = row lane>>2, [2] = row+8
    float i1 = 1.f / dden[2];

    int mlo = m0 + w*16 + (lane >> 2);
    int cb  = 2*(lane & 3);
    float* outb = out + OUTOFF + (size_t)b*CH*NPIX;
    #pragma unroll
    for (int cc = 0; cc < 32; cc++) {
        int c0 = cc*8 + cb;
        outb[(size_t)c0*NPIX + mlo]           = d2[cc][0]*i0 + vmk[c0];
        outb[(size_t)(c0+1)*NPIX + mlo]       = d2[cc][1]*i0 + vmk[c0+1];
        outb[(size_t)c0*NPIX + mlo + 8]       = d2[cc][2]*i1 + vmk[c0];
        outb[(size_t)(c0+1)*NPIX + mlo + 8]   = d2[cc][3]*i1 + vmk[c0+1];
    }
}

// ---------------- launch ----------------
extern "C" void kernel_launch(void* const* d_in, const int* in_sizes, int n_in,
                              void* d_out, int out_size) {
    const float* x  = (const float*)d_in[0];
    const float* wq = (const float*)d_in[1];
    const float* bq = (const float*)d_in[2];
    const float* wk = (const float*)d_in[3];
    const float* bk = (const float*)d_in[4];
    const float* wv = (const float*)d_in[5];
    const float* bv = (const float*)d_in[6];
    const float* wm = (const float*)d_in[7];
    const float* bm = (const float*)d_in[8];
    float* out = (float*)d_out;
    (void)bq; (void)bk;   // q/k biases cancel under spatial centering

    cudaFuncSetAttribute(attn_kernel,  cudaFuncAttributeMaxDynamicSharedMemorySize, SM_TOTAL);
    cudaFuncSetAttribute(gemm2_kernel, cudaFuncAttributeMaxDynamicSharedMemorySize, GEMM_SMEM);

    pack_kernel<<<128, 256>>>(wq, bq, wk, bk, wv, bv, wm, bm);
    xconv_kernel<<<dim3(NPIX/128, CH/64, BATCH), 256>>>(x, out);
    cbias_kernel<<<BATCH, 64>>>();
    gemm2_kernel<<<dim3(NPIX/64, 3, BATCH), 256, GEMM_SMEM>>>();
    masksoftmax_kernel<<<BATCH, 1024>>>();
    vmask_kernel<<<dim3(CH, BATCH), 128>>>();
    qkconv_kernel<<<dim3(NPIX/128, 2, BATCH), 256>>>();
    attn_kernel<<<dim3(NPIX/128, BATCH), 256, SM_TOTAL>>>(out);
}